// round 1
// baseline (speedup 1.0000x reference)
#include <cuda_runtime.h>
#include <math.h>

// ---------------------------------------------------------------------------
// Problem constants
// ---------------------------------------------------------------------------
#define B_ 4
#define L_ 1024
#define DIM_ 1024
#define HEADS_ 16
#define HEAD_DIM_ 64
#define HIDDEN_ 4096
#define NTOK (B_ * L_)          // 4096 tokens
#define SCALE_ 0.125f           // 64^-0.5
#define EPS_ 1e-5f

// ---------------------------------------------------------------------------
// Scratch (device globals; no runtime allocation allowed)
// ---------------------------------------------------------------------------
__device__ float g_skipout[NTOK * DIM_];            // 16 MB
__device__ float g_xln1   [NTOK * DIM_];            // 16 MB
__device__ float g_qkv    [NTOK * 3 * DIM_];        // 48 MB
__device__ float g_scores [(size_t)B_ * HEADS_ * L_ * L_];  // 256 MB
__device__ float g_obuf   [NTOK * DIM_];            // 16 MB
__device__ float g_proj   [NTOK * DIM_];            // 16 MB
__device__ float g_x2     [NTOK * DIM_];            // 16 MB
__device__ float g_h      [NTOK * HIDDEN_];         // 64 MB
__device__ float g_fc2    [NTOK * DIM_];            // 16 MB

// ---------------------------------------------------------------------------
// Generic SGEMM: C[M,N] = A[M,K] @ B[K,N] (+epilogue)
// BM=BN=128, BK=16, 256 threads, 8x8 per-thread microtile.
// All M,N,K used here are multiples of the tile sizes -> no bounds checks.
// ---------------------------------------------------------------------------
template<bool ACC, bool BIAS, bool GELU>
__global__ __launch_bounds__(256)
void sgemm_kernel(const float* __restrict__ A, const float* __restrict__ Bm,
                  const float* __restrict__ bias, float* __restrict__ C,
                  int M, int N, int K) {
    __shared__ float As[16][128];
    __shared__ float Bs[16][128];

    const int tid = threadIdx.x;
    const int bm = blockIdx.y * 128;
    const int bn = blockIdx.x * 128;
    const int tx = tid & 15;
    const int ty = tid >> 4;
    const int tm = ty * 8;
    const int tn = tx * 8;

    float acc[8][8];
#pragma unroll
    for (int i = 0; i < 8; i++)
#pragma unroll
        for (int j = 0; j < 8; j++) acc[i][j] = 0.f;

    for (int k0 = 0; k0 < K; k0 += 16) {
        // A tile: 128 rows x 16 cols = 512 float4
#pragma unroll
        for (int u = 0; u < 2; u++) {
            int idx = u * 256 + tid;
            int row = idx >> 2;
            int c4  = (idx & 3) * 4;
            float4 v = *(const float4*)(A + (size_t)(bm + row) * K + k0 + c4);
            As[c4 + 0][row] = v.x;
            As[c4 + 1][row] = v.y;
            As[c4 + 2][row] = v.z;
            As[c4 + 3][row] = v.w;
        }
        // B tile: 16 rows x 128 cols = 512 float4
#pragma unroll
        for (int u = 0; u < 2; u++) {
            int idx = u * 256 + tid;
            int row = idx >> 5;
            int c4  = (idx & 31) * 4;
            *(float4*)&Bs[row][c4] =
                *(const float4*)(Bm + (size_t)(k0 + row) * N + bn + c4);
        }
        __syncthreads();

#pragma unroll
        for (int k = 0; k < 16; k++) {
            float a[8], b[8];
#pragma unroll
            for (int i = 0; i < 8; i++) a[i] = As[k][tm + i];
#pragma unroll
            for (int j = 0; j < 8; j++) b[j] = Bs[k][tn + j];
#pragma unroll
            for (int i = 0; i < 8; i++)
#pragma unroll
                for (int j = 0; j < 8; j++) acc[i][j] += a[i] * b[j];
        }
        __syncthreads();
    }

#pragma unroll
    for (int i = 0; i < 8; i++) {
#pragma unroll
        for (int j = 0; j < 8; j++) {
            size_t off = (size_t)(bm + tm + i) * N + bn + tn + j;
            float v = acc[i][j];
            if (BIAS) v += bias[bn + tn + j];
            if (ACC)  v += C[off];
            if (GELU) v = 0.5f * v * (1.f + erff(v * 0.70710678118654752f));
            C[off] = v;
        }
    }
}

// ---------------------------------------------------------------------------
// LayerNorm over last dim (1024). One block per row, 256 threads x 4 floats.
// Optional residual add (in + res).
// ---------------------------------------------------------------------------
__global__ __launch_bounds__(256)
void ln_kernel(const float* __restrict__ in, const float* __restrict__ res,
               const float* __restrict__ g, const float* __restrict__ b,
               float* __restrict__ out) {
    const size_t row = blockIdx.x;
    const int t = threadIdx.x;
    float4 x = ((const float4*)(in + row * DIM_))[t];
    if (res != nullptr) {
        float4 r = ((const float4*)(res + row * DIM_))[t];
        x.x += r.x; x.y += r.y; x.z += r.z; x.w += r.w;
    }
    float s  = x.x + x.y + x.z + x.w;
    float ss = x.x * x.x + x.y * x.y + x.z * x.z + x.w * x.w;
#pragma unroll
    for (int o = 16; o > 0; o >>= 1) {
        s  += __shfl_down_sync(0xffffffffu, s,  o);
        ss += __shfl_down_sync(0xffffffffu, ss, o);
    }
    __shared__ float sh_s[8], sh_ss[8];
    __shared__ float sh_mean, sh_rstd;
    int w = t >> 5, lane = t & 31;
    if (lane == 0) { sh_s[w] = s; sh_ss[w] = ss; }
    __syncthreads();
    if (t == 0) {
        float S = 0.f, SS = 0.f;
#pragma unroll
        for (int i = 0; i < 8; i++) { S += sh_s[i]; SS += sh_ss[i]; }
        float m = S * (1.f / DIM_);
        float v = SS * (1.f / DIM_) - m * m;
        sh_mean = m;
        sh_rstd = rsqrtf(v + EPS_);
    }
    __syncthreads();
    float m = sh_mean, rs = sh_rstd;
    float4 gg = ((const float4*)g)[t];
    float4 bb = ((const float4*)b)[t];
    float4 o4;
    o4.x = (x.x - m) * rs * gg.x + bb.x;
    o4.y = (x.y - m) * rs * gg.y + bb.y;
    o4.z = (x.z - m) * rs * gg.z + bb.z;
    o4.w = (x.w - m) * rs * gg.w + bb.w;
    ((float4*)(out + row * DIM_))[t] = o4;
}

// ---------------------------------------------------------------------------
// Attention S = scale * Q K^T.  One block computes a 64x64 tile of one head.
// grid: (L/64, L/64, B*H)
// ---------------------------------------------------------------------------
__global__ __launch_bounds__(256)
void attn_s_kernel(const float* __restrict__ qkv, float* __restrict__ S) {
    __shared__ float Qs[64][64];   // [d][i]
    __shared__ float Ks[64][64];   // [d][j]
    const int tid = threadIdx.x;
    const int bh = blockIdx.z;
    const int b = bh >> 4, h = bh & 15;
    const int i0 = blockIdx.y * 64;
    const int j0 = blockIdx.x * 64;
    const float* qbase = qkv + (size_t)(b * L_) * (3 * DIM_) + h * HEAD_DIM_;
    const float* kbase = qbase + DIM_;

#pragma unroll
    for (int u = 0; u < 4; u++) {
        int idx = u * 256 + tid;        // 0..1023
        int r   = idx >> 4;             // 0..63
        int c4  = (idx & 15) * 4;       // 0..60
        float4 q = *(const float4*)(qbase + (size_t)(i0 + r) * (3 * DIM_) + c4);
        Qs[c4 + 0][r] = q.x; Qs[c4 + 1][r] = q.y;
        Qs[c4 + 2][r] = q.z; Qs[c4 + 3][r] = q.w;
        float4 kk = *(const float4*)(kbase + (size_t)(j0 + r) * (3 * DIM_) + c4);
        Ks[c4 + 0][r] = kk.x; Ks[c4 + 1][r] = kk.y;
        Ks[c4 + 2][r] = kk.z; Ks[c4 + 3][r] = kk.w;
    }
    __syncthreads();

    const int tx = tid & 15, ty = tid >> 4;
    const int tm = ty * 4, tn = tx * 4;
    float acc[4][4];
#pragma unroll
    for (int i = 0; i < 4; i++)
#pragma unroll
        for (int j = 0; j < 4; j++) acc[i][j] = 0.f;

#pragma unroll
    for (int k = 0; k < 64; k++) {
        float a[4], bb[4];
#pragma unroll
        for (int i = 0; i < 4; i++) a[i] = Qs[k][tm + i];
#pragma unroll
        for (int j = 0; j < 4; j++) bb[j] = Ks[k][tn + j];
#pragma unroll
        for (int i = 0; i < 4; i++)
#pragma unroll
            for (int j = 0; j < 4; j++) acc[i][j] += a[i] * bb[j];
    }

#pragma unroll
    for (int i = 0; i < 4; i++)
#pragma unroll
        for (int j = 0; j < 4; j++)
            S[((size_t)bh * L_ + i0 + tm + i) * L_ + j0 + tn + j] =
                acc[i][j] * SCALE_;
}

// ---------------------------------------------------------------------------
// Row softmax over 1024. One block per row. grid: B*H*L
// ---------------------------------------------------------------------------
__global__ __launch_bounds__(256)
void softmax_kernel(float* __restrict__ S) {
    const size_t row = blockIdx.x;
    float* p = S + row * (size_t)L_;
    const int t = threadIdx.x;
    float4 x = ((const float4*)p)[t];
    float mx = fmaxf(fmaxf(x.x, x.y), fmaxf(x.z, x.w));
#pragma unroll
    for (int o = 16; o > 0; o >>= 1)
        mx = fmaxf(mx, __shfl_down_sync(0xffffffffu, mx, o));
    __shared__ float sh[8];
    __shared__ float sh_bc;
    int w = t >> 5, lane = t & 31;
    if (lane == 0) sh[w] = mx;
    __syncthreads();
    if (t == 0) {
        float m = sh[0];
#pragma unroll
        for (int i = 1; i < 8; i++) m = fmaxf(m, sh[i]);
        sh_bc = m;
    }
    __syncthreads();
    mx = sh_bc;
    float4 e;
    e.x = expf(x.x - mx); e.y = expf(x.y - mx);
    e.z = expf(x.z - mx); e.w = expf(x.w - mx);
    float s = e.x + e.y + e.z + e.w;
#pragma unroll
    for (int o = 16; o > 0; o >>= 1)
        s += __shfl_down_sync(0xffffffffu, s, o);
    if (lane == 0) sh[w] = s;
    __syncthreads();
    if (t == 0) {
        float S2 = 0.f;
#pragma unroll
        for (int i = 0; i < 8; i++) S2 += sh[i];
        sh_bc = 1.f / S2;
    }
    __syncthreads();
    float inv = sh_bc;
    e.x *= inv; e.y *= inv; e.z *= inv; e.w *= inv;
    ((float4*)p)[t] = e;
}

// ---------------------------------------------------------------------------
// O = P V per head. One block: 64 query rows x full 64 d.
// grid: (L/64, B*H)
// ---------------------------------------------------------------------------
__global__ __launch_bounds__(256)
void attn_o_kernel(const float* __restrict__ S, const float* __restrict__ qkv,
                   float* __restrict__ O) {
    __shared__ float Ps[64][64];   // [j][i]
    __shared__ float Vs[64][64];   // [j][d]
    const int tid = threadIdx.x;
    const int bh = blockIdx.y;
    const int b = bh >> 4, h = bh & 15;
    const int i0 = blockIdx.x * 64;
    const float* vbase = qkv + (size_t)(b * L_) * (3 * DIM_) + 2 * DIM_ + h * HEAD_DIM_;

    const int tx = tid & 15, ty = tid >> 4;
    const int tm = ty * 4, tn = tx * 4;
    float acc[4][4];
#pragma unroll
    for (int i = 0; i < 4; i++)
#pragma unroll
        for (int j = 0; j < 4; j++) acc[i][j] = 0.f;

    for (int kt = 0; kt < 16; kt++) {
        const int j0 = kt * 64;
#pragma unroll
        for (int u = 0; u < 4; u++) {
            int idx = u * 256 + tid;
            int r   = idx >> 4;
            int c4  = (idx & 15) * 4;
            float4 p = *(const float4*)(S + ((size_t)bh * L_ + i0 + r) * L_ + j0 + c4);
            Ps[c4 + 0][r] = p.x; Ps[c4 + 1][r] = p.y;
            Ps[c4 + 2][r] = p.z; Ps[c4 + 3][r] = p.w;
            float4 v = *(const float4*)(vbase + (size_t)(j0 + r) * (3 * DIM_) + c4);
            *(float4*)&Vs[r][c4] = v;
        }
        __syncthreads();
#pragma unroll
        for (int k = 0; k < 64; k++) {
            float a[4], bb[4];
#pragma unroll
            for (int i = 0; i < 4; i++) a[i] = Ps[k][tm + i];
#pragma unroll
            for (int j = 0; j < 4; j++) bb[j] = Vs[k][tn + j];
#pragma unroll
            for (int i = 0; i < 4; i++)
#pragma unroll
                for (int j = 0; j < 4; j++) acc[i][j] += a[i] * bb[j];
        }
        __syncthreads();
    }

#pragma unroll
    for (int i = 0; i < 4; i++)
#pragma unroll
        for (int j = 0; j < 4; j++)
            O[(size_t)(b * L_ + i0 + tm + i) * DIM_ + h * HEAD_DIM_ + tn + j] =
                acc[i][j];
}

// ---------------------------------------------------------------------------
// Launch
// ---------------------------------------------------------------------------
extern "C" void kernel_launch(void* const* d_in, const int* in_sizes, int n_in,
                              void* d_out, int out_size) {
    const float* x      = (const float*)d_in[0];
    const float* skip   = (const float*)d_in[1];
    const float* skip_w = (const float*)d_in[2];
    const float* skip_b = (const float*)d_in[3];
    const float* ln1_g  = (const float*)d_in[4];
    const float* ln1_b  = (const float*)d_in[5];
    const float* qkv_w  = (const float*)d_in[6];
    const float* proj_w = (const float*)d_in[7];
    const float* proj_b = (const float*)d_in[8];
    const float* ln2_g  = (const float*)d_in[9];
    const float* ln2_b  = (const float*)d_in[10];
    const float* fc1_w  = (const float*)d_in[11];
    const float* fc1_b  = (const float*)d_in[12];
    const float* fc2_w  = (const float*)d_in[13];
    const float* fc2_b  = (const float*)d_in[14];
    const float* ln3_g  = (const float*)d_in[15];
    const float* ln3_b  = (const float*)d_in[16];
    float* out = (float*)d_out;

    float *skipout, *xln1, *qkv, *scores, *obuf, *proj, *x2, *h, *fc2;
    cudaGetSymbolAddress((void**)&skipout, g_skipout);
    cudaGetSymbolAddress((void**)&xln1,    g_xln1);
    cudaGetSymbolAddress((void**)&qkv,     g_qkv);
    cudaGetSymbolAddress((void**)&scores,  g_scores);
    cudaGetSymbolAddress((void**)&obuf,    g_obuf);
    cudaGetSymbolAddress((void**)&proj,    g_proj);
    cudaGetSymbolAddress((void**)&x2,      g_x2);
    cudaGetSymbolAddress((void**)&h,       g_h);
    cudaGetSymbolAddress((void**)&fc2,     g_fc2);

    // 1. skip-concat GEMM: skipout = x @ W[:1024] ; skipout += skip @ W[1024:] + b
    {
        dim3 grid(DIM_ / 128, NTOK / 128);
        sgemm_kernel<false, false, false><<<grid, 256>>>(
            x, skip_w, nullptr, skipout, NTOK, DIM_, DIM_);
        sgemm_kernel<true, true, false><<<grid, 256>>>(
            skip, skip_w + (size_t)DIM_ * DIM_, skip_b, skipout, NTOK, DIM_, DIM_);
    }
    // 2. LN1
    ln_kernel<<<NTOK, 256>>>(skipout, nullptr, ln1_g, ln1_b, xln1);
    // 3. QKV GEMM
    {
        dim3 grid(3 * DIM_ / 128, NTOK / 128);
        sgemm_kernel<false, false, false><<<grid, 256>>>(
            xln1, qkv_w, nullptr, qkv, NTOK, 3 * DIM_, DIM_);
    }
    // 4. S = scale * Q K^T
    {
        dim3 grid(L_ / 64, L_ / 64, B_ * HEADS_);
        attn_s_kernel<<<grid, 256>>>(qkv, scores);
    }
    // 5. softmax rows
    softmax_kernel<<<B_ * HEADS_ * L_, 256>>>(scores);
    // 6. O = P V
    {
        dim3 grid(L_ / 64, B_ * HEADS_);
        attn_o_kernel<<<grid, 256>>>(scores, qkv, obuf);
    }
    // 7. proj GEMM (+bias)
    {
        dim3 grid(DIM_ / 128, NTOK / 128);
        sgemm_kernel<false, true, false><<<grid, 256>>>(
            obuf, proj_w, proj_b, proj, NTOK, DIM_, DIM_);
    }
    // 8. LN2 over (xln1 + proj)
    ln_kernel<<<NTOK, 256>>>(proj, xln1, ln2_g, ln2_b, x2);
    // 9. fc1 GEMM + GELU
    {
        dim3 grid(HIDDEN_ / 128, NTOK / 128);
        sgemm_kernel<false, true, true><<<grid, 256>>>(
            x2, fc1_w, fc1_b, h, NTOK, HIDDEN_, DIM_);
    }
    // 10. fc2 GEMM (+bias)
    {
        dim3 grid(DIM_ / 128, NTOK / 128);
        sgemm_kernel<false, true, false><<<grid, 256>>>(
            h, fc2_w, fc2_b, fc2, NTOK, DIM_, HIDDEN_);
    }
    // 11. LN3 over (x2 + fc2) -> out
    ln_kernel<<<NTOK, 256>>>(fc2, x2, ln3_g, ln3_b, out);
}

// round 2
// speedup vs baseline: 1.6266x; 1.6266x over previous
#include <cuda_runtime.h>
#include <math.h>
#include <stdint.h>

// ---------------------------------------------------------------------------
// Problem constants
// ---------------------------------------------------------------------------
#define B_ 4
#define L_ 1024
#define DIM_ 1024
#define HIDDEN_ 4096
#define NTOK (B_ * L_)          // 4096 tokens
#define SCALE_ 0.125f           // 64^-0.5
#define EPS_ 1e-5f

// ---------------------------------------------------------------------------
// Scratch (device globals; no runtime allocation allowed)
// ---------------------------------------------------------------------------
__device__ float g_skipout[NTOK * DIM_];
__device__ float g_xln1   [NTOK * DIM_];
__device__ float g_qkv    [NTOK * 3 * DIM_];
__device__ float g_scores [(size_t)64 * L_ * L_];
__device__ float g_obuf   [NTOK * DIM_];
__device__ float g_x2     [NTOK * DIM_];
__device__ float g_h      [NTOK * HIDDEN_];
__device__ float g_fc2    [NTOK * DIM_];

// ---------------------------------------------------------------------------
// tf32 helpers
// ---------------------------------------------------------------------------
__device__ __forceinline__ uint32_t f2tf32(float f) {
    uint32_t u;
    asm("cvt.rna.tf32.f32 %0, %1;" : "=r"(u) : "f"(f));
    return u;
}

__device__ __forceinline__ void mma_tf32(
    float& c0, float& c1, float& c2, float& c3,
    uint32_t a0, uint32_t a1, uint32_t a2, uint32_t a3,
    uint32_t b0, uint32_t b1)
{
    asm volatile(
        "mma.sync.aligned.m16n8k8.row.col.f32.tf32.tf32.f32 "
        "{%0,%1,%2,%3}, {%4,%5,%6,%7}, {%8,%9}, {%0,%1,%2,%3};"
        : "+f"(c0), "+f"(c1), "+f"(c2), "+f"(c3)
        : "r"(a0), "r"(a1), "r"(a2), "r"(a3), "r"(b0), "r"(b1));
}

// ---------------------------------------------------------------------------
// tf32 tensor-core GEMM.
// C[M,N] = alpha * A[M,K] @ B[K,N] (+bias) (+acc) (+gelu)
// BM=128, BN in {128, 64}, BK=16, 256 threads (8 warps).
// BN=128: warps 2x4, each 64x32 (4x4 mma tiles of 16x8)
// BN=64 : warps 4x2, each 32x32 (2x4 mma tiles)
// TRANSB: B supplied as [N,K] row-major (used for Q K^T).
// z-batching: per-z offsets = (z>>4)*s1 + (z&15)*s2 for A, B, C.
// All dims are exact multiples of tiles -> no bounds checks.
// ---------------------------------------------------------------------------
template<int BN, bool ACC, bool BIAS, bool GELU, bool TRANSB>
__global__ __launch_bounds__(256)
void gemm_tf32(const float* __restrict__ A, const float* __restrict__ Bm,
               const float* __restrict__ bias, float* __restrict__ C,
               int M, int N, int K, int lda, int ldb, int ldc,
               long zA1, long zA2, long zB1, long zB2, long zC1, long zC2,
               float alpha)
{
    constexpr int BM = 128, BK = 16;
    constexpr int ASR = 136;                 // A smem row stride (conflict-free)
    constexpr int BSR = (BN == 128) ? 136 : 72;
    constexpr int WN  = (BN == 128) ? 4 : 2; // warps along n
    constexpr int WM  = 8 / WN;              // warps along m
    constexpr int WTM = BM / WM;             // warp tile m (64 / 32)
    constexpr int WTN = BN / WN;             // warp tile n (32)
    constexpr int MT  = WTM / 16;            // mma m-tiles per warp
    constexpr int NT  = WTN / 8;             // mma n-tiles per warp (4)

    __shared__ uint32_t As[BK][ASR];         // [k][m], tf32 bits
    __shared__ uint32_t Bs[BK][BSR];         // [k][n], tf32 bits

    const int z = blockIdx.z;
    const float* Az = A  + (long)(z >> 4) * zA1 + (long)(z & 15) * zA2;
    const float* Bz = Bm + (long)(z >> 4) * zB1 + (long)(z & 15) * zB2;
    float*       Cz = C  + (long)(z >> 4) * zC1 + (long)(z & 15) * zC2;

    const int bm = blockIdx.y * BM;
    const int bn = blockIdx.x * BN;
    const int tid  = threadIdx.x;
    const int lane = tid & 31;
    const int warp = tid >> 5;
    const int wm = warp / WN;
    const int wn = warp % WN;
    const int g   = lane >> 2;   // groupID 0..7
    const int tig = lane & 3;    // thread in group 0..3

    float acc[MT][NT][4];
#pragma unroll
    for (int i = 0; i < MT; i++)
#pragma unroll
        for (int j = 0; j < NT; j++)
#pragma unroll
            for (int r = 0; r < 4; r++) acc[i][j][r] = 0.f;

    for (int k0 = 0; k0 < K; k0 += BK) {
        // ---- load A tile: BM x BK, store transposed As[k][m]
#pragma unroll
        for (int u = 0; u < 2; u++) {
            int idx = u * 256 + tid;          // 0..511
            int row = idx >> 2;               // 0..127
            int c4  = (idx & 3) * 4;          // 0,4,8,12
            float4 v = *(const float4*)(Az + (long)(bm + row) * lda + k0 + c4);
            As[c4 + 0][row] = f2tf32(v.x);
            As[c4 + 1][row] = f2tf32(v.y);
            As[c4 + 2][row] = f2tf32(v.z);
            As[c4 + 3][row] = f2tf32(v.w);
        }
        // ---- load B tile: BK x BN (or BN x BK transposed source)
        if (TRANSB) {
#pragma unroll
            for (int u = 0; u < BN / 64; u++) {
                int idx = u * 256 + tid;      // BN*4 total
                int n  = idx >> 2;            // 0..BN-1
                int k4 = (idx & 3) * 4;       // 0,4,8,12
                float4 v = *(const float4*)(Bz + (long)(bn + n) * ldb + k0 + k4);
                Bs[k4 + 0][n] = f2tf32(v.x);
                Bs[k4 + 1][n] = f2tf32(v.y);
                Bs[k4 + 2][n] = f2tf32(v.z);
                Bs[k4 + 3][n] = f2tf32(v.w);
            }
        } else {
#pragma unroll
            for (int u = 0; u < BN / 64; u++) {
                int idx = u * 256 + tid;      // BK*BN/4 total
                int row = idx / (BN / 4);
                int c4  = (idx % (BN / 4)) * 4;
                float4 v = *(const float4*)(Bz + (long)(k0 + row) * ldb + bn + c4);
                Bs[row][c4 + 0] = f2tf32(v.x);
                Bs[row][c4 + 1] = f2tf32(v.y);
                Bs[row][c4 + 2] = f2tf32(v.z);
                Bs[row][c4 + 3] = f2tf32(v.w);
            }
        }
        __syncthreads();

        // ---- compute: 2 k-steps of 8
#pragma unroll
        for (int ks = 0; ks < 2; ks++) {
            const int kk = ks * 8;
            uint32_t a[MT][4], b[NT][2];
#pragma unroll
            for (int mt = 0; mt < MT; mt++) {
                int mb = wm * WTM + mt * 16;
                a[mt][0] = As[kk + tig    ][mb + g    ];
                a[mt][1] = As[kk + tig    ][mb + g + 8];
                a[mt][2] = As[kk + tig + 4][mb + g    ];
                a[mt][3] = As[kk + tig + 4][mb + g + 8];
            }
#pragma unroll
            for (int nt = 0; nt < NT; nt++) {
                int nb = wn * WTN + nt * 8;
                b[nt][0] = Bs[kk + tig    ][nb + g];
                b[nt][1] = Bs[kk + tig + 4][nb + g];
            }
#pragma unroll
            for (int mt = 0; mt < MT; mt++)
#pragma unroll
                for (int nt = 0; nt < NT; nt++)
                    mma_tf32(acc[mt][nt][0], acc[mt][nt][1],
                             acc[mt][nt][2], acc[mt][nt][3],
                             a[mt][0], a[mt][1], a[mt][2], a[mt][3],
                             b[nt][0], b[nt][1]);
        }
        __syncthreads();
    }

    // ---- epilogue
#pragma unroll
    for (int mt = 0; mt < MT; mt++) {
#pragma unroll
        for (int nt = 0; nt < NT; nt++) {
            int r0 = bm + wm * WTM + mt * 16 + g;
            int cn = bn + wn * WTN + nt * 8 + tig * 2;
            float bia0 = 0.f, bia1 = 0.f;
            if (BIAS) { bia0 = bias[cn]; bia1 = bias[cn + 1]; }
#pragma unroll
            for (int half = 0; half < 2; half++) {
                int r = r0 + half * 8;
                float v0 = acc[mt][nt][half * 2 + 0] * alpha + bia0;
                float v1 = acc[mt][nt][half * 2 + 1] * alpha + bia1;
                long off = (long)r * ldc + cn;
                if (ACC) {
                    float2 old = *(const float2*)(Cz + off);
                    v0 += old.x; v1 += old.y;
                }
                if (GELU) {
                    v0 = 0.5f * v0 * (1.f + erff(v0 * 0.70710678118654752f));
                    v1 = 0.5f * v1 * (1.f + erff(v1 * 0.70710678118654752f));
                }
                float2 o; o.x = v0; o.y = v1;
                *(float2*)(Cz + off) = o;
            }
        }
    }
}

// ---------------------------------------------------------------------------
// LayerNorm over last dim (1024). One block per row, 256 threads x 4 floats.
// Optional residual add (in + res).
// ---------------------------------------------------------------------------
__global__ __launch_bounds__(256)
void ln_kernel(const float* __restrict__ in, const float* __restrict__ res,
               const float* __restrict__ g, const float* __restrict__ b,
               float* __restrict__ out) {
    const size_t row = blockIdx.x;
    const int t = threadIdx.x;
    float4 x = ((const float4*)(in + row * DIM_))[t];
    if (res != nullptr) {
        float4 r = ((const float4*)(res + row * DIM_))[t];
        x.x += r.x; x.y += r.y; x.z += r.z; x.w += r.w;
    }
    float s  = x.x + x.y + x.z + x.w;
    float ss = x.x * x.x + x.y * x.y + x.z * x.z + x.w * x.w;
#pragma unroll
    for (int o = 16; o > 0; o >>= 1) {
        s  += __shfl_down_sync(0xffffffffu, s,  o);
        ss += __shfl_down_sync(0xffffffffu, ss, o);
    }
    __shared__ float sh_s[8], sh_ss[8];
    __shared__ float sh_mean, sh_rstd;
    int w = t >> 5, lane = t & 31;
    if (lane == 0) { sh_s[w] = s; sh_ss[w] = ss; }
    __syncthreads();
    if (t == 0) {
        float S = 0.f, SS = 0.f;
#pragma unroll
        for (int i = 0; i < 8; i++) { S += sh_s[i]; SS += sh_ss[i]; }
        float m = S * (1.f / DIM_);
        float v = SS * (1.f / DIM_) - m * m;
        sh_mean = m;
        sh_rstd = rsqrtf(v + EPS_);
    }
    __syncthreads();
    float m = sh_mean, rs = sh_rstd;
    float4 gg = ((const float4*)g)[t];
    float4 bb = ((const float4*)b)[t];
    float4 o4;
    o4.x = (x.x - m) * rs * gg.x + bb.x;
    o4.y = (x.y - m) * rs * gg.y + bb.y;
    o4.z = (x.z - m) * rs * gg.z + bb.z;
    o4.w = (x.w - m) * rs * gg.w + bb.w;
    ((float4*)(out + row * DIM_))[t] = o4;
}

// ---------------------------------------------------------------------------
// Row softmax over 1024. One block per row. grid: B*H*L
// ---------------------------------------------------------------------------
__global__ __launch_bounds__(256)
void softmax_kernel(float* __restrict__ S) {
    const size_t row = blockIdx.x;
    float* p = S + row * (size_t)L_;
    const int t = threadIdx.x;
    float4 x = ((const float4*)p)[t];
    float mx = fmaxf(fmaxf(x.x, x.y), fmaxf(x.z, x.w));
#pragma unroll
    for (int o = 16; o > 0; o >>= 1)
        mx = fmaxf(mx, __shfl_down_sync(0xffffffffu, mx, o));
    __shared__ float sh[8];
    __shared__ float sh_bc;
    int w = t >> 5, lane = t & 31;
    if (lane == 0) sh[w] = mx;
    __syncthreads();
    if (t == 0) {
        float m = sh[0];
#pragma unroll
        for (int i = 1; i < 8; i++) m = fmaxf(m, sh[i]);
        sh_bc = m;
    }
    __syncthreads();
    mx = sh_bc;
    float4 e;
    e.x = expf(x.x - mx); e.y = expf(x.y - mx);
    e.z = expf(x.z - mx); e.w = expf(x.w - mx);
    float s = e.x + e.y + e.z + e.w;
#pragma unroll
    for (int o = 16; o > 0; o >>= 1)
        s += __shfl_down_sync(0xffffffffu, s, o);
    if (lane == 0) sh[w] = s;
    __syncthreads();
    if (t == 0) {
        float S2 = 0.f;
#pragma unroll
        for (int i = 0; i < 8; i++) S2 += sh[i];
        sh_bc = 1.f / S2;
    }
    __syncthreads();
    float inv = sh_bc;
    e.x *= inv; e.y *= inv; e.z *= inv; e.w *= inv;
    ((float4*)p)[t] = e;
}

// ---------------------------------------------------------------------------
// Launch
// ---------------------------------------------------------------------------
extern "C" void kernel_launch(void* const* d_in, const int* in_sizes, int n_in,
                              void* d_out, int out_size) {
    const float* x      = (const float*)d_in[0];
    const float* skip   = (const float*)d_in[1];
    const float* skip_w = (const float*)d_in[2];
    const float* skip_b = (const float*)d_in[3];
    const float* ln1_g  = (const float*)d_in[4];
    const float* ln1_b  = (const float*)d_in[5];
    const float* qkv_w  = (const float*)d_in[6];
    const float* proj_w = (const float*)d_in[7];
    const float* proj_b = (const float*)d_in[8];
    const float* ln2_g  = (const float*)d_in[9];
    const float* ln2_b  = (const float*)d_in[10];
    const float* fc1_w  = (const float*)d_in[11];
    const float* fc1_b  = (const float*)d_in[12];
    const float* fc2_w  = (const float*)d_in[13];
    const float* fc2_b  = (const float*)d_in[14];
    const float* ln3_g  = (const float*)d_in[15];
    const float* ln3_b  = (const float*)d_in[16];
    float* out = (float*)d_out;

    float *skipout, *xln1, *qkv, *scores, *obuf, *x2, *h, *fc2;
    cudaGetSymbolAddress((void**)&skipout, g_skipout);
    cudaGetSymbolAddress((void**)&xln1,    g_xln1);
    cudaGetSymbolAddress((void**)&qkv,     g_qkv);
    cudaGetSymbolAddress((void**)&scores,  g_scores);
    cudaGetSymbolAddress((void**)&obuf,    g_obuf);
    cudaGetSymbolAddress((void**)&x2,      g_x2);
    cudaGetSymbolAddress((void**)&h,       g_h);
    cudaGetSymbolAddress((void**)&fc2,     g_fc2);

    const long LL = (long)L_ * L_;

    // 1. skip-concat GEMM: skipout = x @ W[:1024]; skipout += skip @ W[1024:] + b
    {
        dim3 grid(DIM_ / 128, NTOK / 128, 1);
        gemm_tf32<128, false, false, false, false><<<grid, 256>>>(
            x, skip_w, nullptr, skipout, NTOK, DIM_, DIM_,
            DIM_, DIM_, DIM_, 0, 0, 0, 0, 0, 0, 1.f);
        gemm_tf32<128, true, true, false, false><<<grid, 256>>>(
            skip, skip_w + (size_t)DIM_ * DIM_, skip_b, skipout, NTOK, DIM_, DIM_,
            DIM_, DIM_, DIM_, 0, 0, 0, 0, 0, 0, 1.f);
    }
    // 2. LN1
    ln_kernel<<<NTOK, 256>>>(skipout, nullptr, ln1_g, ln1_b, xln1);
    // 3. QKV GEMM
    {
        dim3 grid(3 * DIM_ / 128, NTOK / 128, 1);
        gemm_tf32<128, false, false, false, false><<<grid, 256>>>(
            xln1, qkv_w, nullptr, qkv, NTOK, 3 * DIM_, DIM_,
            DIM_, 3 * DIM_, 3 * DIM_, 0, 0, 0, 0, 0, 0, 1.f);
    }
    // 4. S = scale * Q K^T  (z = b*16+h; A=Q strided, B=K^T)
    {
        dim3 grid(L_ / 128, L_ / 128, 64);
        gemm_tf32<128, false, false, false, true><<<grid, 256>>>(
            qkv, qkv + DIM_, nullptr, scores, L_, L_, 64,
            3 * DIM_, 3 * DIM_, L_,
            (long)L_ * 3 * DIM_, 64,          // A z-offsets (b, h)
            (long)L_ * 3 * DIM_, 64,          // B z-offsets
            16 * LL, LL,                      // C z-offsets
            SCALE_);
    }
    // 5. softmax rows
    softmax_kernel<<<64 * L_, 256>>>(scores);
    // 6. O = P V  (per head, N=64)
    {
        dim3 grid(1, L_ / 128, 64);
        gemm_tf32<64, false, false, false, false><<<grid, 256>>>(
            scores, qkv + 2 * DIM_, nullptr, obuf, L_, 64, L_,
            L_, 3 * DIM_, DIM_,
            16 * LL, LL,                      // A z-offsets
            (long)L_ * 3 * DIM_, 64,          // B z-offsets
            (long)L_ * DIM_, 64,              // C z-offsets
            1.f);
    }
    // 7. proj GEMM (+bias), accumulate residual later via LN residual input
    {
        dim3 grid(DIM_ / 128, NTOK / 128, 1);
        gemm_tf32<128, false, true, false, false><<<grid, 256>>>(
            obuf, proj_w, proj_b, fc2 /* reuse as temp */, NTOK, DIM_, DIM_,
            DIM_, DIM_, DIM_, 0, 0, 0, 0, 0, 0, 1.f);
    }
    // 8. LN2 over (proj_out + xln1)
    ln_kernel<<<NTOK, 256>>>(fc2, xln1, ln2_g, ln2_b, x2);
    // 9. fc1 GEMM + bias + GELU
    {
        dim3 grid(HIDDEN_ / 128, NTOK / 128, 1);
        gemm_tf32<128, false, true, true, false><<<grid, 256>>>(
            x2, fc1_w, fc1_b, h, NTOK, HIDDEN_, DIM_,
            DIM_, HIDDEN_, HIDDEN_, 0, 0, 0, 0, 0, 0, 1.f);
    }
    // 10. fc2 GEMM (+bias)
    {
        dim3 grid(DIM_ / 128, NTOK / 128, 1);
        gemm_tf32<128, false, true, false, false><<<grid, 256>>>(
            h, fc2_w, fc2_b, fc2, NTOK, DIM_, HIDDEN_,
            HIDDEN_, DIM_, DIM_, 0, 0, 0, 0, 0, 0, 1.f);
    }
    // 11. LN3 over (x2 + fc2) -> out
    ln_kernel<<<NTOK, 256>>>(fc2, x2, ln3_g, ln3_b, out);
}

// round 3
// speedup vs baseline: 2.4822x; 1.5260x over previous
#include <cuda_runtime.h>
#include <math.h>
#include <stdint.h>

// ---------------------------------------------------------------------------
// Problem constants
// ---------------------------------------------------------------------------
#define B_ 4
#define L_ 1024
#define DIM_ 1024
#define HIDDEN_ 4096
#define NTOK (B_ * L_)          // 4096 tokens
#define SCALE_ 0.125f           // 64^-0.5
#define EPS_ 1e-5f

// ---------------------------------------------------------------------------
// Scratch (device globals; no runtime allocation allowed)
// ---------------------------------------------------------------------------
__device__ float g_skipout[NTOK * DIM_];
__device__ float g_xln1   [NTOK * DIM_];
__device__ float g_qkv    [NTOK * 3 * DIM_];
__device__ float g_scores [(size_t)64 * L_ * L_];
__device__ float g_obuf   [NTOK * DIM_];
__device__ float g_x2     [NTOK * DIM_];
__device__ float g_h      [NTOK * HIDDEN_];
__device__ float g_fc2    [NTOK * DIM_];

// ---------------------------------------------------------------------------
// tf32 helpers
// ---------------------------------------------------------------------------
__device__ __forceinline__ uint32_t f2tf32(float f) {
    uint32_t u;
    asm("cvt.rna.tf32.f32 %0, %1;" : "=r"(u) : "f"(f));
    return u;
}

__device__ __forceinline__ void mma_tf32(
    float& c0, float& c1, float& c2, float& c3,
    uint32_t a0, uint32_t a1, uint32_t a2, uint32_t a3,
    uint32_t b0, uint32_t b1)
{
    asm volatile(
        "mma.sync.aligned.m16n8k8.row.col.f32.tf32.tf32.f32 "
        "{%0,%1,%2,%3}, {%4,%5,%6,%7}, {%8,%9}, {%0,%1,%2,%3};"
        : "+f"(c0), "+f"(c1), "+f"(c2), "+f"(c3)
        : "r"(a0), "r"(a1), "r"(a2), "r"(a3), "r"(b0), "r"(b1));
}

// ---------------------------------------------------------------------------
// tf32 tensor-core GEMM.
// C[M,N] = alpha * A[M,K] @ B[K,N] (+bias) (+acc) (+gelu)
// BM=128, BN in {128, 64}, BK=16, 256 threads (8 warps).
// BN=128: warps 2x4, each 64x32 (4x4 mma tiles of 16x8)
// BN=64 : warps 4x2, each 32x32 (2x4 mma tiles)
// TRANSB: B supplied as [N,K] row-major (used for Q K^T).
// z-batching: per-z offsets = (z>>4)*s1 + (z&15)*s2 for A, B, C.
// All dims are exact multiples of tiles -> no bounds checks.
// ---------------------------------------------------------------------------
template<int BN, bool ACC, bool BIAS, bool GELU, bool TRANSB>
__global__ __launch_bounds__(256)
void gemm_tf32(const float* __restrict__ A, const float* __restrict__ Bm,
               const float* __restrict__ bias, float* __restrict__ C,
               int M, int N, int K, int lda, int ldb, int ldc,
               long zA1, long zA2, long zB1, long zB2, long zC1, long zC2,
               float alpha)
{
    constexpr int BM = 128, BK = 16;
    constexpr int ASR = 136;                 // A smem row stride (conflict-free)
    constexpr int BSR = (BN == 128) ? 136 : 72;
    constexpr int WN  = (BN == 128) ? 4 : 2; // warps along n
    constexpr int WM  = 8 / WN;              // warps along m
    constexpr int WTM = BM / WM;             // warp tile m (64 / 32)
    constexpr int WTN = BN / WN;             // warp tile n (32)
    constexpr int MT  = WTM / 16;            // mma m-tiles per warp
    constexpr int NT  = WTN / 8;             // mma n-tiles per warp (4)

    __shared__ uint32_t As[BK][ASR];         // [k][m], tf32 bits
    __shared__ uint32_t Bs[BK][BSR];         // [k][n], tf32 bits

    const int z = blockIdx.z;
    const float* Az = A  + (long)(z >> 4) * zA1 + (long)(z & 15) * zA2;
    const float* Bz = Bm + (long)(z >> 4) * zB1 + (long)(z & 15) * zB2;
    float*       Cz = C  + (long)(z >> 4) * zC1 + (long)(z & 15) * zC2;

    const int bm = blockIdx.y * BM;
    const int bn = blockIdx.x * BN;
    const int tid  = threadIdx.x;
    const int lane = tid & 31;
    const int warp = tid >> 5;
    const int wm = warp / WN;
    const int wn = warp % WN;
    const int g   = lane >> 2;   // groupID 0..7
    const int tig = lane & 3;    // thread in group 0..3

    float acc[MT][NT][4];
#pragma unroll
    for (int i = 0; i < MT; i++)
#pragma unroll
        for (int j = 0; j < NT; j++)
#pragma unroll
            for (int r = 0; r < 4; r++) acc[i][j][r] = 0.f;

    for (int k0 = 0; k0 < K; k0 += BK) {
        // ---- load A tile: BM x BK, store transposed As[k][m]
#pragma unroll
        for (int u = 0; u < 2; u++) {
            int idx = u * 256 + tid;          // 0..511
            int row = idx >> 2;               // 0..127
            int c4  = (idx & 3) * 4;          // 0,4,8,12
            float4 v = *(const float4*)(Az + (long)(bm + row) * lda + k0 + c4);
            As[c4 + 0][row] = f2tf32(v.x);
            As[c4 + 1][row] = f2tf32(v.y);
            As[c4 + 2][row] = f2tf32(v.z);
            As[c4 + 3][row] = f2tf32(v.w);
        }
        // ---- load B tile: BK x BN (or BN x BK transposed source)
        if (TRANSB) {
#pragma unroll
            for (int u = 0; u < BN / 64; u++) {
                int idx = u * 256 + tid;      // BN*4 total
                int n  = idx >> 2;            // 0..BN-1
                int k4 = (idx & 3) * 4;       // 0,4,8,12
                float4 v = *(const float4*)(Bz + (long)(bn + n) * ldb + k0 + k4);
                Bs[k4 + 0][n] = f2tf32(v.x);
                Bs[k4 + 1][n] = f2tf32(v.y);
                Bs[k4 + 2][n] = f2tf32(v.z);
                Bs[k4 + 3][n] = f2tf32(v.w);
            }
        } else {
#pragma unroll
            for (int u = 0; u < BN / 64; u++) {
                int idx = u * 256 + tid;      // BK*BN/4 total
                int row = idx / (BN / 4);
                int c4  = (idx % (BN / 4)) * 4;
                float4 v = *(const float4*)(Bz + (long)(k0 + row) * ldb + bn + c4);
                Bs[row][c4 + 0] = f2tf32(v.x);
                Bs[row][c4 + 1] = f2tf32(v.y);
                Bs[row][c4 + 2] = f2tf32(v.z);
                Bs[row][c4 + 3] = f2tf32(v.w);
            }
        }
        __syncthreads();

        // ---- compute: 2 k-steps of 8
#pragma unroll
        for (int ks = 0; ks < 2; ks++) {
            const int kk = ks * 8;
            uint32_t a[MT][4], b[NT][2];
#pragma unroll
            for (int mt = 0; mt < MT; mt++) {
                int mb = wm * WTM + mt * 16;
                a[mt][0] = As[kk + tig    ][mb + g    ];
                a[mt][1] = As[kk + tig    ][mb + g + 8];
                a[mt][2] = As[kk + tig + 4][mb + g    ];
                a[mt][3] = As[kk + tig + 4][mb + g + 8];
            }
#pragma unroll
            for (int nt = 0; nt < NT; nt++) {
                int nb = wn * WTN + nt * 8;
                b[nt][0] = Bs[kk + tig    ][nb + g];
                b[nt][1] = Bs[kk + tig + 4][nb + g];
            }
#pragma unroll
            for (int mt = 0; mt < MT; mt++)
#pragma unroll
                for (int nt = 0; nt < NT; nt++)
                    mma_tf32(acc[mt][nt][0], acc[mt][nt][1],
                             acc[mt][nt][2], acc[mt][nt][3],
                             a[mt][0], a[mt][1], a[mt][2], a[mt][3],
                             b[nt][0], b[nt][1]);
        }
        __syncthreads();
    }

    // ---- epilogue
#pragma unroll
    for (int mt = 0; mt < MT; mt++) {
#pragma unroll
        for (int nt = 0; nt < NT; nt++) {
            int r0 = bm + wm * WTM + mt * 16 + g;
            int cn = bn + wn * WTN + nt * 8 + tig * 2;
            float bia0 = 0.f, bia1 = 0.f;
            if (BIAS) { bia0 = bias[cn]; bia1 = bias[cn + 1]; }
#pragma unroll
            for (int half = 0; half < 2; half++) {
                int r = r0 + half * 8;
                float v0 = acc[mt][nt][half * 2 + 0] * alpha + bia0;
                float v1 = acc[mt][nt][half * 2 + 1] * alpha + bia1;
                long off = (long)r * ldc + cn;
                if (ACC) {
                    float2 old = *(const float2*)(Cz + off);
                    v0 += old.x; v1 += old.y;
                }
                if (GELU) {
                    v0 = 0.5f * v0 * (1.f + erff(v0 * 0.70710678118654752f));
                    v1 = 0.5f * v1 * (1.f + erff(v1 * 0.70710678118654752f));
                }
                float2 o; o.x = v0; o.y = v1;
                *(float2*)(Cz + off) = o;
            }
        }
    }
}

// ---------------------------------------------------------------------------
// LayerNorm over last dim (1024). One block per row, 256 threads x 4 floats.
// Optional residual add (in + res).
// ---------------------------------------------------------------------------
__global__ __launch_bounds__(256)
void ln_kernel(const float* __restrict__ in, const float* __restrict__ res,
               const float* __restrict__ g, const float* __restrict__ b,
               float* __restrict__ out) {
    const size_t row = blockIdx.x;
    const int t = threadIdx.x;
    float4 x = ((const float4*)(in + row * DIM_))[t];
    if (res != nullptr) {
        float4 r = ((const float4*)(res + row * DIM_))[t];
        x.x += r.x; x.y += r.y; x.z += r.z; x.w += r.w;
    }
    float s  = x.x + x.y + x.z + x.w;
    float ss = x.x * x.x + x.y * x.y + x.z * x.z + x.w * x.w;
#pragma unroll
    for (int o = 16; o > 0; o >>= 1) {
        s  += __shfl_down_sync(0xffffffffu, s,  o);
        ss += __shfl_down_sync(0xffffffffu, ss, o);
    }
    __shared__ float sh_s[8], sh_ss[8];
    __shared__ float sh_mean, sh_rstd;
    int w = t >> 5, lane = t & 31;
    if (lane == 0) { sh_s[w] = s; sh_ss[w] = ss; }
    __syncthreads();
    if (t == 0) {
        float S = 0.f, SS = 0.f;
#pragma unroll
        for (int i = 0; i < 8; i++) { S += sh_s[i]; SS += sh_ss[i]; }
        float m = S * (1.f / DIM_);
        float v = SS * (1.f / DIM_) - m * m;
        sh_mean = m;
        sh_rstd = rsqrtf(v + EPS_);
    }
    __syncthreads();
    float m = sh_mean, rs = sh_rstd;
    float4 gg = ((const float4*)g)[t];
    float4 bb = ((const float4*)b)[t];
    float4 o4;
    o4.x = (x.x - m) * rs * gg.x + bb.x;
    o4.y = (x.y - m) * rs * gg.y + bb.y;
    o4.z = (x.z - m) * rs * gg.z + bb.z;
    o4.w = (x.w - m) * rs * gg.w + bb.w;
    ((float4*)(out + row * DIM_))[t] = o4;
}

// ---------------------------------------------------------------------------
// Row softmax over 1024. One block per row. grid: B*H*L
// ---------------------------------------------------------------------------
__global__ __launch_bounds__(256)
void softmax_kernel(float* __restrict__ S) {
    const size_t row = blockIdx.x;
    float* p = S + row * (size_t)L_;
    const int t = threadIdx.x;
    float4 x = ((const float4*)p)[t];
    float mx = fmaxf(fmaxf(x.x, x.y), fmaxf(x.z, x.w));
#pragma unroll
    for (int o = 16; o > 0; o >>= 1)
        mx = fmaxf(mx, __shfl_down_sync(0xffffffffu, mx, o));
    __shared__ float sh[8];
    __shared__ float sh_bc;
    int w = t >> 5, lane = t & 31;
    if (lane == 0) sh[w] = mx;
    __syncthreads();
    if (t == 0) {
        float m = sh[0];
#pragma unroll
        for (int i = 1; i < 8; i++) m = fmaxf(m, sh[i]);
        sh_bc = m;
    }
    __syncthreads();
    mx = sh_bc;
    float4 e;
    e.x = expf(x.x - mx); e.y = expf(x.y - mx);
    e.z = expf(x.z - mx); e.w = expf(x.w - mx);
    float s = e.x + e.y + e.z + e.w;
#pragma unroll
    for (int o = 16; o > 0; o >>= 1)
        s += __shfl_down_sync(0xffffffffu, s, o);
    if (lane == 0) sh[w] = s;
    __syncthreads();
    if (t == 0) {
        float S2 = 0.f;
#pragma unroll
        for (int i = 0; i < 8; i++) S2 += sh[i];
        sh_bc = 1.f / S2;
    }
    __syncthreads();
    float inv = sh_bc;
    e.x *= inv; e.y *= inv; e.z *= inv; e.w *= inv;
    ((float4*)p)[t] = e;
}

// ---------------------------------------------------------------------------
// Launch
// ---------------------------------------------------------------------------
extern "C" void kernel_launch(void* const* d_in, const int* in_sizes, int n_in,
                              void* d_out, int out_size) {
    const float* x      = (const float*)d_in[0];
    const float* skip   = (const float*)d_in[1];
    const float* skip_w = (const float*)d_in[2];
    const float* skip_b = (const float*)d_in[3];
    const float* ln1_g  = (const float*)d_in[4];
    const float* ln1_b  = (const float*)d_in[5];
    const float* qkv_w  = (const float*)d_in[6];
    const float* proj_w = (const float*)d_in[7];
    const float* proj_b = (const float*)d_in[8];
    const float* ln2_g  = (const float*)d_in[9];
    const float* ln2_b  = (const float*)d_in[10];
    const float* fc1_w  = (const float*)d_in[11];
    const float* fc1_b  = (const float*)d_in[12];
    const float* fc2_w  = (const float*)d_in[13];
    const float* fc2_b  = (const float*)d_in[14];
    const float* ln3_g  = (const float*)d_in[15];
    const float* ln3_b  = (const float*)d_in[16];
    float* out = (float*)d_out;

    float *skipout, *xln1, *qkv, *scores, *obuf, *x2, *h, *fc2;
    cudaGetSymbolAddress((void**)&skipout, g_skipout);
    cudaGetSymbolAddress((void**)&xln1,    g_xln1);
    cudaGetSymbolAddress((void**)&qkv,     g_qkv);
    cudaGetSymbolAddress((void**)&scores,  g_scores);
    cudaGetSymbolAddress((void**)&obuf,    g_obuf);
    cudaGetSymbolAddress((void**)&x2,      g_x2);
    cudaGetSymbolAddress((void**)&h,       g_h);
    cudaGetSymbolAddress((void**)&fc2,     g_fc2);

    const long LL = (long)L_ * L_;

    // 1. skip-concat GEMM: skipout = x @ W[:1024]; skipout += skip @ W[1024:] + b
    {
        dim3 grid(DIM_ / 128, NTOK / 128, 1);
        gemm_tf32<128, false, false, false, false><<<grid, 256>>>(
            x, skip_w, nullptr, skipout, NTOK, DIM_, DIM_,
            DIM_, DIM_, DIM_, 0, 0, 0, 0, 0, 0, 1.f);
        gemm_tf32<128, true, true, false, false><<<grid, 256>>>(
            skip, skip_w + (size_t)DIM_ * DIM_, skip_b, skipout, NTOK, DIM_, DIM_,
            DIM_, DIM_, DIM_, 0, 0, 0, 0, 0, 0, 1.f);
    }
    // 2. LN1
    ln_kernel<<<NTOK, 256>>>(skipout, nullptr, ln1_g, ln1_b, xln1);
    // 3. QKV GEMM
    {
        dim3 grid(3 * DIM_ / 128, NTOK / 128, 1);
        gemm_tf32<128, false, false, false, false><<<grid, 256>>>(
            xln1, qkv_w, nullptr, qkv, NTOK, 3 * DIM_, DIM_,
            DIM_, 3 * DIM_, 3 * DIM_, 0, 0, 0, 0, 0, 0, 1.f);
    }
    // 4. S = scale * Q K^T  (z = b*16+h; A=Q strided, B=K^T)
    {
        dim3 grid(L_ / 128, L_ / 128, 64);
        gemm_tf32<128, false, false, false, true><<<grid, 256>>>(
            qkv, qkv + DIM_, nullptr, scores, L_, L_, 64,
            3 * DIM_, 3 * DIM_, L_,
            (long)L_ * 3 * DIM_, 64,          // A z-offsets (b, h)
            (long)L_ * 3 * DIM_, 64,          // B z-offsets
            16 * LL, LL,                      // C z-offsets
            SCALE_);
    }
    // 5. softmax rows
    softmax_kernel<<<64 * L_, 256>>>(scores);
    // 6. O = P V  (per head, N=64)
    {
        dim3 grid(1, L_ / 128, 64);
        gemm_tf32<64, false, false, false, false><<<grid, 256>>>(
            scores, qkv + 2 * DIM_, nullptr, obuf, L_, 64, L_,
            L_, 3 * DIM_, DIM_,
            16 * LL, LL,                      // A z-offsets
            (long)L_ * 3 * DIM_, 64,          // B z-offsets
            (long)L_ * DIM_, 64,              // C z-offsets
            1.f);
    }
    // 7. proj GEMM (+bias), accumulate residual later via LN residual input
    {
        dim3 grid(DIM_ / 128, NTOK / 128, 1);
        gemm_tf32<128, false, true, false, false><<<grid, 256>>>(
            obuf, proj_w, proj_b, fc2 /* reuse as temp */, NTOK, DIM_, DIM_,
            DIM_, DIM_, DIM_, 0, 0, 0, 0, 0, 0, 1.f);
    }
    // 8. LN2 over (proj_out + xln1)
    ln_kernel<<<NTOK, 256>>>(fc2, xln1, ln2_g, ln2_b, x2);
    // 9. fc1 GEMM + bias + GELU
    {
        dim3 grid(HIDDEN_ / 128, NTOK / 128, 1);
        gemm_tf32<128, false, true, true, false><<<grid, 256>>>(
            x2, fc1_w, fc1_b, h, NTOK, HIDDEN_, DIM_,
            DIM_, HIDDEN_, HIDDEN_, 0, 0, 0, 0, 0, 0, 1.f);
    }
    // 10. fc2 GEMM (+bias)
    {
        dim3 grid(DIM_ / 128, NTOK / 128, 1);
        gemm_tf32<128, false, true, false, false><<<grid, 256>>>(
            h, fc2_w, fc2_b, fc2, NTOK, DIM_, HIDDEN_,
            HIDDEN_, DIM_, DIM_, 0, 0, 0, 0, 0, 0, 1.f);
    }
    // 11. LN3 over (x2 + fc2) -> out
    ln_kernel<<<NTOK, 256>>>(fc2, x2, ln3_g, ln3_b, out);
}

// round 7
// speedup vs baseline: 5.1610x; 2.0792x over previous
#include <cuda_runtime.h>
#include <cuda_fp16.h>
#include <math.h>
#include <stdint.h>

typedef __half half_t;

#define NTOK 4096
#define DIM_ 1024
#define LSEQ 1024
#define HID_ 4096
#define EPS_ 1e-5f
#define SCALE_ 0.125f

// ---------------------------------------------------------------------------
// Device scratch (no runtime allocation allowed)
// ---------------------------------------------------------------------------
__device__ float g_skipout[NTOK * DIM_];
__device__ float g_xln1   [NTOK * DIM_];
__device__ float g_scores [(size_t)64 * LSEQ * LSEQ];
__device__ float g_x2     [NTOK * DIM_];
__device__ float g_tmp    [NTOK * DIM_];

__device__ half_t g_xh  [NTOK * DIM_];
__device__ half_t g_skh [NTOK * DIM_];
__device__ half_t g_x1h [NTOK * DIM_];
__device__ half_t g_qkvh[NTOK * 3 * DIM_];
__device__ half_t g_P   [(size_t)64 * LSEQ * LSEQ];
__device__ half_t g_vt  [64 * 64 * LSEQ];
__device__ half_t g_obh [NTOK * DIM_];
__device__ half_t g_x2h [NTOK * DIM_];
__device__ half_t g_hh  [(size_t)NTOK * HID_];
// transposed weights [N][K] fp16
__device__ half_t g_wsk [DIM_ * 2 * DIM_];
__device__ half_t g_wqkv[3 * DIM_ * DIM_];
__device__ half_t g_wpr [DIM_ * DIM_];
__device__ half_t g_wf1 [(size_t)HID_ * DIM_];
__device__ half_t g_wf2 [(size_t)DIM_ * HID_];

// ---------------------------------------------------------------------------
// PTX helpers (all plain-sm_103-legal: Ampere-era instructions)
// ---------------------------------------------------------------------------
__device__ __forceinline__ uint32_t smem_u32(const void* p) {
    uint32_t a;
    asm("{ .reg .u64 t; cvta.to.shared.u64 t, %1; cvt.u32.u64 %0, t; }"
        : "=r"(a) : "l"(p));
    return a;
}
__device__ __forceinline__ void cp16(uint32_t dst, const void* src) {
    asm volatile("cp.async.cg.shared.global [%0], [%1], 16;"
                 :: "r"(dst), "l"(src));
}
__device__ __forceinline__ void cp_commit() {
    asm volatile("cp.async.commit_group;" ::: "memory");
}
template<int N>
__device__ __forceinline__ void cp_wait() {
    asm volatile("cp.async.wait_group %0;" :: "n"(N) : "memory");
}
__device__ __forceinline__ void ldm_x4(uint32_t& r0, uint32_t& r1,
                                       uint32_t& r2, uint32_t& r3, uint32_t a) {
    asm volatile("ldmatrix.sync.aligned.m8n8.x4.shared.b16 {%0,%1,%2,%3}, [%4];"
                 : "=r"(r0), "=r"(r1), "=r"(r2), "=r"(r3) : "r"(a));
}
__device__ __forceinline__ void mma_f16(
    float& c0, float& c1, float& c2, float& c3,
    uint32_t a0, uint32_t a1, uint32_t a2, uint32_t a3,
    uint32_t b0, uint32_t b1)
{
    asm volatile(
        "mma.sync.aligned.m16n8k16.row.col.f32.f16.f16.f32 "
        "{%0,%1,%2,%3}, {%4,%5,%6,%7}, {%8,%9}, {%0,%1,%2,%3};"
        : "+f"(c0), "+f"(c1), "+f"(c2), "+f"(c3)
        : "r"(a0), "r"(a1), "r"(a2), "r"(a3), "r"(b0), "r"(b1));
}

// ---------------------------------------------------------------------------
// fp16 tensor-core GEMM: C[M,N] = alpha*(A[M,K] @ B[N,K]^T) (+bias)(+gelu)
// A, B fp16 K-major. BM=128, BN in {128,64}, BK=32, cp.async double buffer,
// ldmatrix fragments, 256 threads (8 warps), 2 CTAs/SM.
// z-batching: offsets = (z>>4)*s1 + (z&15)*s2.
// ---------------------------------------------------------------------------
struct GemmP {
    const half_t *a, *a2, *b;
    const float* bias;
    float* out_f;
    half_t* out_h;
    int K, lda, ldb, ldc, ksplit;
    long zA1, zA2, zB1, zB2, zC1, zC2;
    float alpha;
};

template<int BN, bool CONCAT, bool BIAS, bool GELU, bool OUTF32>
__global__ void __launch_bounds__(256, 2) gemm_fp16(GemmP p) {
    constexpr int BK  = 32;
    constexpr int PAD = 40;                  // half units; 80B row stride
    constexpr int WN  = (BN == 128) ? 4 : 2;
    constexpr int WM  = 8 / WN;
    constexpr int WTM = 128 / WM;            // 64 / 32
    constexpr int WTN = BN / WN;             // 32
    constexpr int MT  = WTM / 16;            // 4 / 2
    constexpr int NT  = WTN / 8;             // 4

    __shared__ half_t As[2][128][PAD];
    __shared__ half_t Bs[2][BN][PAD];

    const int tid = threadIdx.x, lane = tid & 31, warp = tid >> 5;
    const int wm = warp / WN, wn = warp % WN;
    const int g = lane >> 2, tig = lane & 3;
    const int z = blockIdx.z;
    const int bm = blockIdx.y * 128, bn = blockIdx.x * BN;

    const half_t* Az = p.a + (long)(z >> 4) * p.zA1 + (long)(z & 15) * p.zA2;
    const half_t* Bz = p.b + (long)(z >> 4) * p.zB1 + (long)(z & 15) * p.zB2;
    const long coff = (long)(z >> 4) * p.zC1 + (long)(z & 15) * p.zC2;

    const uint32_t sA = smem_u32(As), sB = smem_u32(Bs);
    const int nchunk = p.K / BK;

    // tile loader via cp.async
    auto load_tile = [&](int s, int c) {
        const half_t* asrc; int ka;
        if (CONCAT && c * BK >= p.ksplit) { asrc = p.a2; ka = c * BK - p.ksplit; }
        else                               { asrc = Az;  ka = c * BK; }
#pragma unroll
        for (int u = 0; u < 2; u++) {
            int ch = u * 256 + tid;          // 512 chunks of 16B
            int row = ch >> 2, o = ch & 3;
            cp16(sA + ((s * 128 + row) * PAD + o * 8) * 2,
                 asrc + (size_t)(bm + row) * p.lda + ka + o * 8);
        }
#pragma unroll
        for (int u = 0; u < BN / 64; u++) {
            int ch = u * 256 + tid;
            int row = ch >> 2, o = ch & 3;
            cp16(sB + ((s * BN + row) * PAD + o * 8) * 2,
                 Bz + (size_t)(bn + row) * p.ldb + c * BK + o * 8);
        }
        cp_commit();
    };

    float acc[MT][NT][4];
#pragma unroll
    for (int i = 0; i < MT; i++)
#pragma unroll
        for (int j = 0; j < NT; j++)
#pragma unroll
            for (int r = 0; r < 4; r++) acc[i][j][r] = 0.f;

    load_tile(0, 0);
    load_tile(1, 1);

    // ldmatrix per-lane address components
    const int a_row = lane & 15;             // row within 16-row tile
    const int a_ko  = (lane >> 4) * 8;       // k offset 0/8
    const int b_ro  = (lane >> 4) * 8 + (lane & 7);  // row offset within 16-n pair
    const int b_ko  = ((lane >> 3) & 1) * 8;

    for (int c = 0; c < nchunk; c++) {
        const int s = c & 1;
        if (c == nchunk - 1) cp_wait<0>(); else cp_wait<1>();
        __syncthreads();

#pragma unroll
        for (int ks = 0; ks < 2; ks++) {
            const int kk = ks * 16;
            uint32_t a[MT][4], b[NT][2];
#pragma unroll
            for (int mt = 0; mt < MT; mt++) {
                int row = wm * WTM + mt * 16 + a_row;
                uint32_t addr = sA + ((s * 128 + row) * PAD + kk + a_ko) * 2;
                ldm_x4(a[mt][0], a[mt][1], a[mt][2], a[mt][3], addr);
            }
#pragma unroll
            for (int pr = 0; pr < NT / 2; pr++) {
                int row = wn * WTN + pr * 16 + b_ro;
                uint32_t addr = sB + ((s * BN + row) * PAD + kk + b_ko) * 2;
                ldm_x4(b[2 * pr][0], b[2 * pr][1],
                       b[2 * pr + 1][0], b[2 * pr + 1][1], addr);
            }
#pragma unroll
            for (int mt = 0; mt < MT; mt++)
#pragma unroll
                for (int nt = 0; nt < NT; nt++)
                    mma_f16(acc[mt][nt][0], acc[mt][nt][1],
                            acc[mt][nt][2], acc[mt][nt][3],
                            a[mt][0], a[mt][1], a[mt][2], a[mt][3],
                            b[nt][0], b[nt][1]);
        }
        __syncthreads();
        if (c + 2 < nchunk) load_tile(s, c + 2);
    }

    // epilogue
#pragma unroll
    for (int mt = 0; mt < MT; mt++) {
#pragma unroll
        for (int nt = 0; nt < NT; nt++) {
            int r0 = bm + wm * WTM + mt * 16 + g;
            int cn = bn + wn * WTN + nt * 8 + tig * 2;
            float bia0 = 0.f, bia1 = 0.f;
            if (BIAS) { bia0 = p.bias[cn]; bia1 = p.bias[cn + 1]; }
#pragma unroll
            for (int hf = 0; hf < 2; hf++) {
                int r = r0 + hf * 8;
                float v0 = acc[mt][nt][hf * 2 + 0] * p.alpha + bia0;
                float v1 = acc[mt][nt][hf * 2 + 1] * p.alpha + bia1;
                if (GELU) {
                    v0 = 0.5f * v0 * (1.f + erff(v0 * 0.70710678118654752f));
                    v1 = 0.5f * v1 * (1.f + erff(v1 * 0.70710678118654752f));
                }
                long off = coff + (long)r * p.ldc + cn;
                if (OUTF32) {
                    float2 o; o.x = v0; o.y = v1;
                    *(float2*)(p.out_f + off) = o;
                } else {
                    __half2 o;
                    o.x = __float2half_rn(v0); o.y = __float2half_rn(v1);
                    *(__half2*)(p.out_h + off) = o;
                }
            }
        }
    }
}

// ---------------------------------------------------------------------------
// fp32 -> fp16 elementwise convert
// ---------------------------------------------------------------------------
__global__ __launch_bounds__(256)
void cvt_half(const float* __restrict__ in, half_t* __restrict__ out) {
    size_t i = ((size_t)blockIdx.x * 256 + threadIdx.x) * 4;
    float4 x = *(const float4*)(in + i);
    __half2 a, b;
    a.x = __float2half_rn(x.x); a.y = __float2half_rn(x.y);
    b.x = __float2half_rn(x.z); b.y = __float2half_rn(x.w);
    *(__half2*)(out + i) = a;
    *(__half2*)(out + i + 2) = b;
}

// ---------------------------------------------------------------------------
// Weight transpose+convert: fp32 [K,N] -> fp16 [N][K]
// ---------------------------------------------------------------------------
__global__ __launch_bounds__(256)
void wtrans_kernel(const float* __restrict__ w, half_t* __restrict__ o,
                   int K, int N) {
    __shared__ float t[32][33];
    int k0 = blockIdx.x * 32, n0 = blockIdx.y * 32;
    int tx = threadIdx.x & 31, ty = threadIdx.x >> 5;
    for (int i = ty; i < 32; i += 8)
        t[i][tx] = w[(size_t)(k0 + i) * N + n0 + tx];
    __syncthreads();
    for (int i = ty; i < 32; i += 8)
        o[(size_t)(n0 + i) * K + k0 + tx] = __float2half_rn(t[tx][i]);
}

// V transpose per head: qkv fp16 -> vt [z][64][1024]
__global__ __launch_bounds__(256)
void vt_kernel(const half_t* __restrict__ qkv, half_t* __restrict__ vt) {
    __shared__ half_t t[32][33];
    int z = blockIdx.z, b = z >> 4, h = z & 15;
    int t0 = blockIdx.x * 32, d0 = blockIdx.y * 32;
    int tx = threadIdx.x & 31, ty = threadIdx.x >> 5;
    for (int i = ty; i < 32; i += 8)
        t[i][tx] = qkv[(size_t)(b * LSEQ + t0 + i) * 3072 + 2048 + h * 64 + d0 + tx];
    __syncthreads();
    for (int i = ty; i < 32; i += 8)
        vt[(size_t)z * 64 * LSEQ + (size_t)(d0 + i) * LSEQ + t0 + tx] = t[tx][i];
}

// ---------------------------------------------------------------------------
// LayerNorm (+residual): out fp32 (optional) + fp16 copy (optional)
// ---------------------------------------------------------------------------
__global__ __launch_bounds__(256)
void ln_kernel(const float* __restrict__ in, const float* __restrict__ res,
               const float* __restrict__ g, const float* __restrict__ b,
               float* __restrict__ out_f, half_t* __restrict__ out_h) {
    const size_t row = blockIdx.x;
    const int t = threadIdx.x;
    float4 x = ((const float4*)(in + row * DIM_))[t];
    if (res) {
        float4 r = ((const float4*)(res + row * DIM_))[t];
        x.x += r.x; x.y += r.y; x.z += r.z; x.w += r.w;
    }
    float s = x.x + x.y + x.z + x.w;
    float ss = x.x*x.x + x.y*x.y + x.z*x.z + x.w*x.w;
#pragma unroll
    for (int o = 16; o > 0; o >>= 1) {
        s  += __shfl_down_sync(0xffffffffu, s, o);
        ss += __shfl_down_sync(0xffffffffu, ss, o);
    }
    __shared__ float shs[8], shss[8], shm, shr;
    int w = t >> 5, lane = t & 31;
    if (lane == 0) { shs[w] = s; shss[w] = ss; }
    __syncthreads();
    if (t == 0) {
        float S = 0, SS = 0;
#pragma unroll
        for (int i = 0; i < 8; i++) { S += shs[i]; SS += shss[i]; }
        float m = S * (1.f / DIM_);
        shm = m; shr = rsqrtf(SS * (1.f / DIM_) - m * m + EPS_);
    }
    __syncthreads();
    float m = shm, rs = shr;
    float4 gg = ((const float4*)g)[t], bb = ((const float4*)b)[t];
    float4 o4;
    o4.x = (x.x-m)*rs*gg.x + bb.x; o4.y = (x.y-m)*rs*gg.y + bb.y;
    o4.z = (x.z-m)*rs*gg.z + bb.z; o4.w = (x.w-m)*rs*gg.w + bb.w;
    if (out_f) ((float4*)(out_f + row * DIM_))[t] = o4;
    if (out_h) {
        __half2 a, bb2;
        a.x = __float2half_rn(o4.x); a.y = __float2half_rn(o4.y);
        bb2.x = __float2half_rn(o4.z); bb2.y = __float2half_rn(o4.w);
        size_t i = row * DIM_ + t * 4;
        *(__half2*)(out_h + i) = a;
        *(__half2*)(out_h + i + 2) = bb2;
    }
}

// ---------------------------------------------------------------------------
// Softmax row (1024): fp32 scores in -> fp16 P out
// ---------------------------------------------------------------------------
__global__ __launch_bounds__(256)
void softmax_kernel(const float* __restrict__ S, half_t* __restrict__ P) {
    const size_t row = blockIdx.x;
    const float* p = S + row * (size_t)LSEQ;
    const int t = threadIdx.x;
    float4 x = ((const float4*)p)[t];
    float mx = fmaxf(fmaxf(x.x, x.y), fmaxf(x.z, x.w));
#pragma unroll
    for (int o = 16; o > 0; o >>= 1)
        mx = fmaxf(mx, __shfl_down_sync(0xffffffffu, mx, o));
    __shared__ float sh[8], shbc;
    int w = t >> 5, lane = t & 31;
    if (lane == 0) sh[w] = mx;
    __syncthreads();
    if (t == 0) {
        float m = sh[0];
#pragma unroll
        for (int i = 1; i < 8; i++) m = fmaxf(m, sh[i]);
        shbc = m;
    }
    __syncthreads();
    mx = shbc;
    float4 e;
    e.x = expf(x.x-mx); e.y = expf(x.y-mx); e.z = expf(x.z-mx); e.w = expf(x.w-mx);
    float s = e.x + e.y + e.z + e.w;
#pragma unroll
    for (int o = 16; o > 0; o >>= 1)
        s += __shfl_down_sync(0xffffffffu, s, o);
    if (lane == 0) sh[w] = s;
    __syncthreads();
    if (t == 0) {
        float S2 = 0;
#pragma unroll
        for (int i = 0; i < 8; i++) S2 += sh[i];
        shbc = 1.f / S2;
    }
    __syncthreads();
    float inv = shbc;
    __half2 a, b;
    a.x = __float2half_rn(e.x * inv); a.y = __float2half_rn(e.y * inv);
    b.x = __float2half_rn(e.z * inv); b.y = __float2half_rn(e.w * inv);
    size_t i = row * (size_t)LSEQ + t * 4;
    *(__half2*)(P + i) = a;
    *(__half2*)(P + i + 2) = b;
}

// ---------------------------------------------------------------------------
// Launch
// ---------------------------------------------------------------------------
#define GA(v, sym) cudaGetSymbolAddress((void**)&v, sym)

extern "C" void kernel_launch(void* const* d_in, const int* in_sizes, int n_in,
                              void* d_out, int out_size) {
    const float* x      = (const float*)d_in[0];
    const float* skip   = (const float*)d_in[1];
    const float* skip_w = (const float*)d_in[2];
    const float* skip_b = (const float*)d_in[3];
    const float* ln1_g  = (const float*)d_in[4];
    const float* ln1_b  = (const float*)d_in[5];
    const float* qkv_w  = (const float*)d_in[6];
    const float* proj_w = (const float*)d_in[7];
    const float* proj_b = (const float*)d_in[8];
    const float* ln2_g  = (const float*)d_in[9];
    const float* ln2_b  = (const float*)d_in[10];
    const float* fc1_w  = (const float*)d_in[11];
    const float* fc1_b  = (const float*)d_in[12];
    const float* fc2_w  = (const float*)d_in[13];
    const float* fc2_b  = (const float*)d_in[14];
    const float* ln3_g  = (const float*)d_in[15];
    const float* ln3_b  = (const float*)d_in[16];
    float* out = (float*)d_out;

    float *skipout, *xln1, *scores, *x2, *tmp;
    GA(skipout, g_skipout); GA(xln1, g_xln1); GA(scores, g_scores);
    GA(x2, g_x2); GA(tmp, g_tmp);
    half_t *xh,*skh,*x1h,*qkvh,*P,*vt,*obh,*x2h,*hh;
    GA(xh,g_xh); GA(skh,g_skh); GA(x1h,g_x1h); GA(qkvh,g_qkvh);
    GA(P,g_P); GA(vt,g_vt); GA(obh,g_obh); GA(x2h,g_x2h); GA(hh,g_hh);
    half_t *wsk,*wqkv,*wpr,*wf1,*wf2;
    GA(wsk,g_wsk); GA(wqkv,g_wqkv); GA(wpr,g_wpr); GA(wf1,g_wf1); GA(wf2,g_wf2);

    const long LL = (long)LSEQ * LSEQ;

    // ---- prep: transpose+convert weights, convert inputs
    wtrans_kernel<<<dim3(64,32), 256>>>(skip_w, wsk, 2*DIM_, DIM_);
    wtrans_kernel<<<dim3(32,96), 256>>>(qkv_w,  wqkv, DIM_, 3*DIM_);
    wtrans_kernel<<<dim3(32,32), 256>>>(proj_w, wpr,  DIM_, DIM_);
    wtrans_kernel<<<dim3(32,128),256>>>(fc1_w,  wf1,  DIM_, HID_);
    wtrans_kernel<<<dim3(128,32),256>>>(fc2_w,  wf2,  HID_, DIM_);
    cvt_half<<<NTOK*DIM_/1024, 256>>>(x,    xh);
    cvt_half<<<NTOK*DIM_/1024, 256>>>(skip, skh);

    GemmP p;

    // 1. skip-concat GEMM (K=2048, A switches x->skip at k=1024)
    memset(&p, 0, sizeof(p)); p.alpha = 1.f;
    p.a = xh; p.a2 = skh; p.b = wsk; p.bias = skip_b; p.out_f = skipout;
    p.K = 2048; p.lda = DIM_; p.ldb = 2048; p.ldc = DIM_; p.ksplit = 1024;
    gemm_fp16<128,true,true,false,true><<<dim3(8,32,1), 256>>>(p);
    // 2. LN1 -> xln1 f32 + x1h fp16
    ln_kernel<<<NTOK,256>>>(skipout, nullptr, ln1_g, ln1_b, xln1, x1h);
    // 3. QKV GEMM -> qkvh fp16
    memset(&p, 0, sizeof(p)); p.alpha = 1.f;
    p.a = x1h; p.b = wqkv; p.out_h = qkvh;
    p.K = DIM_; p.lda = DIM_; p.ldb = DIM_; p.ldc = 3*DIM_;
    gemm_fp16<128,false,false,false,false><<<dim3(24,32,1), 256>>>(p);
    // 4. V^T per head
    vt_kernel<<<dim3(32,2,64), 256>>>(qkvh, vt);
    // 5. S = scale * Q K^T  -> scores f32
    memset(&p, 0, sizeof(p)); p.alpha = SCALE_;
    p.a = qkvh; p.b = qkvh + DIM_; p.out_f = scores;
    p.K = 64; p.lda = 3*DIM_; p.ldb = 3*DIM_; p.ldc = LSEQ;
    p.zA1 = (long)LSEQ*3*DIM_; p.zA2 = 64;
    p.zB1 = (long)LSEQ*3*DIM_; p.zB2 = 64;
    p.zC1 = 16L*LL; p.zC2 = LL;
    gemm_fp16<128,false,false,false,true><<<dim3(8,8,64), 256>>>(p);
    // 6. softmax -> P fp16
    softmax_kernel<<<64*LSEQ, 256>>>(scores, P);
    // 7. O = P V -> obh fp16
    memset(&p, 0, sizeof(p)); p.alpha = 1.f;
    p.a = P; p.b = vt; p.out_h = obh;
    p.K = LSEQ; p.lda = LSEQ; p.ldb = LSEQ; p.ldc = DIM_;
    p.zA1 = 16L*LL; p.zA2 = LL;
    p.zB1 = 16L*64*LSEQ; p.zB2 = 64L*LSEQ;
    p.zC1 = (long)LSEQ*DIM_; p.zC2 = 64;
    gemm_fp16<64,false,false,false,false><<<dim3(1,8,64), 256>>>(p);
    // 8. proj -> tmp f32
    memset(&p, 0, sizeof(p)); p.alpha = 1.f;
    p.a = obh; p.b = wpr; p.bias = proj_b; p.out_f = tmp;
    p.K = DIM_; p.lda = DIM_; p.ldb = DIM_; p.ldc = DIM_;
    gemm_fp16<128,false,true,false,true><<<dim3(8,32,1), 256>>>(p);
    // 9. LN2 over (tmp + xln1) -> x2 f32 + x2h fp16
    ln_kernel<<<NTOK,256>>>(tmp, xln1, ln2_g, ln2_b, x2, x2h);
    // 10. fc1 + bias + GELU -> hh fp16
    memset(&p, 0, sizeof(p)); p.alpha = 1.f;
    p.a = x2h; p.b = wf1; p.bias = fc1_b; p.out_h = hh;
    p.K = DIM_; p.lda = DIM_; p.ldb = DIM_; p.ldc = HID_;
    gemm_fp16<128,false,true,true,false><<<dim3(32,32,1), 256>>>(p);
    // 11. fc2 -> tmp f32
    memset(&p, 0, sizeof(p)); p.alpha = 1.f;
    p.a = hh; p.b = wf2; p.bias = fc2_b; p.out_f = tmp;
    p.K = HID_; p.lda = HID_; p.ldb = HID_; p.ldc = DIM_;
    gemm_fp16<128,false,true,false,true><<<dim3(8,32,1), 256>>>(p);
    // 12. LN3 over (tmp + x2) -> out
    ln_kernel<<<NTOK,256>>>(tmp, x2, ln3_g, ln3_b, out, nullptr);
}

// round 12
// speedup vs baseline: 6.3569x; 1.2317x over previous
#include <cuda_runtime.h>
#include <cuda_fp16.h>
#include <math.h>
#include <stdint.h>

typedef __half half_t;

#define NTOK 4096
#define DIM_ 1024
#define LSEQ 1024
#define HID_ 4096
#define EPS_ 1e-5f
#define SCALE_ 0.125f

// ---------------------------------------------------------------------------
// Device scratch (no runtime allocation allowed)
// ---------------------------------------------------------------------------
__device__ float g_skipout[NTOK * DIM_];
__device__ float g_xln1   [NTOK * DIM_];
__device__ float g_x2     [NTOK * DIM_];
__device__ float g_tmp    [NTOK * DIM_];

__device__ half_t g_xh  [NTOK * DIM_];
__device__ half_t g_skh [NTOK * DIM_];
__device__ half_t g_x1h [NTOK * DIM_];
__device__ half_t g_qkvh[NTOK * 3 * DIM_];
__device__ half_t g_obh [NTOK * DIM_];
__device__ half_t g_x2h [NTOK * DIM_];
__device__ half_t g_hh  [(size_t)NTOK * HID_];
// transposed weights [N][K] fp16
__device__ half_t g_wsk [DIM_ * 2 * DIM_];
__device__ half_t g_wqkv[3 * DIM_ * DIM_];
__device__ half_t g_wpr [DIM_ * DIM_];
__device__ half_t g_wf1 [(size_t)HID_ * DIM_];
__device__ half_t g_wf2 [(size_t)DIM_ * HID_];

// ---------------------------------------------------------------------------
// PTX helpers (plain-sm_103-legal)
// ---------------------------------------------------------------------------
__device__ __forceinline__ uint32_t smem_u32(const void* p) {
    uint32_t a;
    asm("{ .reg .u64 t; cvta.to.shared.u64 t, %1; cvt.u32.u64 %0, t; }"
        : "=r"(a) : "l"(p));
    return a;
}
__device__ __forceinline__ void cp16(uint32_t dst, const void* src) {
    asm volatile("cp.async.cg.shared.global [%0], [%1], 16;"
                 :: "r"(dst), "l"(src));
}
__device__ __forceinline__ void cp_commit() {
    asm volatile("cp.async.commit_group;" ::: "memory");
}
template<int N>
__device__ __forceinline__ void cp_wait() {
    asm volatile("cp.async.wait_group %0;" :: "n"(N) : "memory");
}
__device__ __forceinline__ void ldm_x4(uint32_t& r0, uint32_t& r1,
                                       uint32_t& r2, uint32_t& r3, uint32_t a) {
    asm volatile("ldmatrix.sync.aligned.m8n8.x4.shared.b16 {%0,%1,%2,%3}, [%4];"
                 : "=r"(r0), "=r"(r1), "=r"(r2), "=r"(r3) : "r"(a));
}
__device__ __forceinline__ void ldm_x4_t(uint32_t& r0, uint32_t& r1,
                                         uint32_t& r2, uint32_t& r3, uint32_t a) {
    asm volatile("ldmatrix.sync.aligned.m8n8.x4.trans.shared.b16 {%0,%1,%2,%3}, [%4];"
                 : "=r"(r0), "=r"(r1), "=r"(r2), "=r"(r3) : "r"(a));
}
__device__ __forceinline__ void mma_f16(
    float& c0, float& c1, float& c2, float& c3,
    uint32_t a0, uint32_t a1, uint32_t a2, uint32_t a3,
    uint32_t b0, uint32_t b1)
{
    asm volatile(
        "mma.sync.aligned.m16n8k16.row.col.f32.f16.f16.f32 "
        "{%0,%1,%2,%3}, {%4,%5,%6,%7}, {%8,%9}, {%0,%1,%2,%3};"
        : "+f"(c0), "+f"(c1), "+f"(c2), "+f"(c3)
        : "r"(a0), "r"(a1), "r"(a2), "r"(a3), "r"(b0), "r"(b1));
}
// pack two floats into fp16x2 bits: lo -> low half, hi -> high half
__device__ __forceinline__ uint32_t f2_to_h2(float lo, float hi) {
    uint32_t r;
    asm("cvt.rn.f16x2.f32 %0, %1, %2;" : "=r"(r) : "f"(hi), "f"(lo));
    return r;
}

// ---------------------------------------------------------------------------
// fp16 tensor-core GEMM (round-7, passing)
// ---------------------------------------------------------------------------
struct GemmP {
    const half_t *a, *a2, *b;
    const float* bias;
    float* out_f;
    half_t* out_h;
    int K, lda, ldb, ldc, ksplit;
    long zA1, zA2, zB1, zB2, zC1, zC2;
    float alpha;
};

template<int BN, bool CONCAT, bool BIAS, bool GELU, bool OUTF32>
__global__ void __launch_bounds__(256, 2) gemm_fp16(GemmP p) {
    constexpr int BK  = 32;
    constexpr int PAD = 40;
    constexpr int WN  = (BN == 128) ? 4 : 2;
    constexpr int WM  = 8 / WN;
    constexpr int WTM = 128 / WM;
    constexpr int WTN = BN / WN;
    constexpr int MT  = WTM / 16;
    constexpr int NT  = WTN / 8;

    __shared__ half_t As[2][128][PAD];
    __shared__ half_t Bs[2][BN][PAD];

    const int tid = threadIdx.x, lane = tid & 31, warp = tid >> 5;
    const int wm = warp / WN, wn = warp % WN;
    const int g = lane >> 2, tig = lane & 3;
    const int z = blockIdx.z;
    const int bm = blockIdx.y * 128, bn = blockIdx.x * BN;

    const half_t* Az = p.a + (long)(z >> 4) * p.zA1 + (long)(z & 15) * p.zA2;
    const half_t* Bz = p.b + (long)(z >> 4) * p.zB1 + (long)(z & 15) * p.zB2;
    const long coff = (long)(z >> 4) * p.zC1 + (long)(z & 15) * p.zC2;

    const uint32_t sA = smem_u32(As), sB = smem_u32(Bs);
    const int nchunk = p.K / BK;

    auto load_tile = [&](int s, int c) {
        const half_t* asrc; int ka;
        if (CONCAT && c * BK >= p.ksplit) { asrc = p.a2; ka = c * BK - p.ksplit; }
        else                               { asrc = Az;  ka = c * BK; }
#pragma unroll
        for (int u = 0; u < 2; u++) {
            int ch = u * 256 + tid;
            int row = ch >> 2, o = ch & 3;
            cp16(sA + ((s * 128 + row) * PAD + o * 8) * 2,
                 asrc + (size_t)(bm + row) * p.lda + ka + o * 8);
        }
#pragma unroll
        for (int u = 0; u < BN / 64; u++) {
            int ch = u * 256 + tid;
            int row = ch >> 2, o = ch & 3;
            cp16(sB + ((s * BN + row) * PAD + o * 8) * 2,
                 Bz + (size_t)(bn + row) * p.ldb + c * BK + o * 8);
        }
        cp_commit();
    };

    float acc[MT][NT][4];
#pragma unroll
    for (int i = 0; i < MT; i++)
#pragma unroll
        for (int j = 0; j < NT; j++)
#pragma unroll
            for (int r = 0; r < 4; r++) acc[i][j][r] = 0.f;

    load_tile(0, 0);
    load_tile(1, 1);

    const int a_row = lane & 15;
    const int a_ko  = (lane >> 4) * 8;
    const int b_ro  = (lane >> 4) * 8 + (lane & 7);
    const int b_ko  = ((lane >> 3) & 1) * 8;

    for (int c = 0; c < nchunk; c++) {
        const int s = c & 1;
        if (c == nchunk - 1) cp_wait<0>(); else cp_wait<1>();
        __syncthreads();

#pragma unroll
        for (int ks = 0; ks < 2; ks++) {
            const int kk = ks * 16;
            uint32_t a[MT][4], b[NT][2];
#pragma unroll
            for (int mt = 0; mt < MT; mt++) {
                int row = wm * WTM + mt * 16 + a_row;
                uint32_t addr = sA + ((s * 128 + row) * PAD + kk + a_ko) * 2;
                ldm_x4(a[mt][0], a[mt][1], a[mt][2], a[mt][3], addr);
            }
#pragma unroll
            for (int pr = 0; pr < NT / 2; pr++) {
                int row = wn * WTN + pr * 16 + b_ro;
                uint32_t addr = sB + ((s * BN + row) * PAD + kk + b_ko) * 2;
                ldm_x4(b[2 * pr][0], b[2 * pr][1],
                       b[2 * pr + 1][0], b[2 * pr + 1][1], addr);
            }
#pragma unroll
            for (int mt = 0; mt < MT; mt++)
#pragma unroll
                for (int nt = 0; nt < NT; nt++)
                    mma_f16(acc[mt][nt][0], acc[mt][nt][1],
                            acc[mt][nt][2], acc[mt][nt][3],
                            a[mt][0], a[mt][1], a[mt][2], a[mt][3],
                            b[nt][0], b[nt][1]);
        }
        __syncthreads();
        if (c + 2 < nchunk) load_tile(s, c + 2);
    }

#pragma unroll
    for (int mt = 0; mt < MT; mt++) {
#pragma unroll
        for (int nt = 0; nt < NT; nt++) {
            int r0 = bm + wm * WTM + mt * 16 + g;
            int cn = bn + wn * WTN + nt * 8 + tig * 2;
            float bia0 = 0.f, bia1 = 0.f;
            if (BIAS) { bia0 = p.bias[cn]; bia1 = p.bias[cn + 1]; }
#pragma unroll
            for (int hf = 0; hf < 2; hf++) {
                int r = r0 + hf * 8;
                float v0 = acc[mt][nt][hf * 2 + 0] * p.alpha + bia0;
                float v1 = acc[mt][nt][hf * 2 + 1] * p.alpha + bia1;
                if (GELU) {
                    v0 = 0.5f * v0 * (1.f + erff(v0 * 0.70710678118654752f));
                    v1 = 0.5f * v1 * (1.f + erff(v1 * 0.70710678118654752f));
                }
                long off = coff + (long)r * p.ldc + cn;
                if (OUTF32) {
                    float2 o; o.x = v0; o.y = v1;
                    *(float2*)(p.out_f + off) = o;
                } else {
                    __half2 o;
                    o.x = __float2half_rn(v0); o.y = __float2half_rn(v1);
                    *(__half2*)(p.out_h + off) = o;
                }
            }
        }
    }
}

// ---------------------------------------------------------------------------
// Fused flash attention: per block = (128 query rows) x (1 head).
// Reads qkvh [tok][3072] (q|k|v, head-interleaved 64-wide), writes
// obh [tok][1024] at column h*64. Online softmax, P in registers,
// V^T via ldmatrix.trans. grid (L/128, B*H), 256 threads.
// ---------------------------------------------------------------------------
#define FA_PAD 72
#define FA_SMEM ((128 * FA_PAD + 2 * 64 * FA_PAD + 2 * 64 * FA_PAD) * 2)

__global__ void __launch_bounds__(256) fattn_kernel(
    const half_t* __restrict__ qkv, half_t* __restrict__ o_out)
{
    extern __shared__ half_t fsm[];
    half_t* Qs = fsm;                          // [128][FA_PAD]
    half_t* Ks = Qs + 128 * FA_PAD;            // [2][64][FA_PAD]
    half_t* Vs = Ks + 2 * 64 * FA_PAD;         // [2][64][FA_PAD]

    const int tid = threadIdx.x, lane = tid & 31, w = tid >> 5;
    const int g = lane >> 2, tig = lane & 3;
    const int z = blockIdx.y, b = z >> 4, h = z & 15;
    const int i0 = blockIdx.x * 128;

    const half_t* qb = qkv + (size_t)(b * LSEQ) * 3072 + h * 64;
    const half_t* kb = qb + 1024;
    const half_t* vb = qb + 2048;

    const uint32_t sQ = smem_u32(Qs), sK = smem_u32(Ks), sV = smem_u32(Vs);

    auto load_kv = [&](int s, int j0) {
#pragma unroll
        for (int u = 0; u < 2; u++) {
            int ch = u * 256 + tid;            // 512 chunks, 64 rows x 8
            int row = ch >> 3, off = (ch & 7) * 8;
            cp16(sK + ((s * 64 + row) * FA_PAD + off) * 2,
                 kb + (size_t)(j0 + row) * 3072 + off);
        }
#pragma unroll
        for (int u = 0; u < 2; u++) {
            int ch = u * 256 + tid;
            int row = ch >> 3, off = (ch & 7) * 8;
            cp16(sV + ((s * 64 + row) * FA_PAD + off) * 2,
                 vb + (size_t)(j0 + row) * 3072 + off);
        }
        cp_commit();
    };

    // Q tile + first KV tile in group 0; second KV tile group 1
#pragma unroll
    for (int u = 0; u < 4; u++) {
        int ch = u * 256 + tid;                // 1024 chunks, 128 rows x 8
        int row = ch >> 3, off = (ch & 7) * 8;
        cp16(sQ + (row * FA_PAD + off) * 2,
             qb + (size_t)(i0 + row) * 3072 + off);
    }
    load_kv(0, 0);      // commits group containing Q + KV0
    load_kv(1, 64);     // group 1

    float m0 = -1e30f, m1 = -1e30f, l0 = 0.f, l1 = 0.f;
    float oacc[8][4];
#pragma unroll
    for (int nt = 0; nt < 8; nt++)
#pragma unroll
        for (int r = 0; r < 4; r++) oacc[nt][r] = 0.f;

    const int a_row = lane & 15;
    const int a_ko  = (lane >> 4) * 8;
    const int b_ro  = (lane >> 4) * 8 + (lane & 7);
    const int b_ko  = ((lane >> 3) & 1) * 8;

    for (int c = 0; c < 16; c++) {
        const int s = c & 1;
        if (c == 15) cp_wait<0>(); else cp_wait<1>();
        __syncthreads();

        // ---- S = Q K^T for this tile (per warp: 16 rows x 64 keys)
        float sacc[8][4];
#pragma unroll
        for (int nt = 0; nt < 8; nt++)
#pragma unroll
            for (int r = 0; r < 4; r++) sacc[nt][r] = 0.f;

#pragma unroll
        for (int k4 = 0; k4 < 4; k4++) {
            const int kk = k4 * 16;
            uint32_t qa[4], kf[8][2];
            ldm_x4(qa[0], qa[1], qa[2], qa[3],
                   sQ + ((w * 16 + a_row) * FA_PAD + kk + a_ko) * 2);
#pragma unroll
            for (int pr = 0; pr < 4; pr++)
                ldm_x4(kf[2 * pr][0], kf[2 * pr][1],
                       kf[2 * pr + 1][0], kf[2 * pr + 1][1],
                       sK + ((s * 64 + pr * 16 + b_ro) * FA_PAD + kk + b_ko) * 2);
#pragma unroll
            for (int nt = 0; nt < 8; nt++)
                mma_f16(sacc[nt][0], sacc[nt][1], sacc[nt][2], sacc[nt][3],
                        qa[0], qa[1], qa[2], qa[3], kf[nt][0], kf[nt][1]);
        }

        // ---- online softmax (rows g and g+8 of this warp's 16)
#pragma unroll
        for (int nt = 0; nt < 8; nt++)
#pragma unroll
            for (int r = 0; r < 4; r++) sacc[nt][r] *= SCALE_;

        float cm0 = -1e30f, cm1 = -1e30f;
#pragma unroll
        for (int nt = 0; nt < 8; nt++) {
            cm0 = fmaxf(cm0, fmaxf(sacc[nt][0], sacc[nt][1]));
            cm1 = fmaxf(cm1, fmaxf(sacc[nt][2], sacc[nt][3]));
        }
        cm0 = fmaxf(cm0, __shfl_xor_sync(0xffffffffu, cm0, 1));
        cm0 = fmaxf(cm0, __shfl_xor_sync(0xffffffffu, cm0, 2));
        cm1 = fmaxf(cm1, __shfl_xor_sync(0xffffffffu, cm1, 1));
        cm1 = fmaxf(cm1, __shfl_xor_sync(0xffffffffu, cm1, 2));

        float mn0 = fmaxf(m0, cm0), mn1 = fmaxf(m1, cm1);
        float cr0 = __expf(m0 - mn0), cr1 = __expf(m1 - mn1);
        m0 = mn0; m1 = mn1;

        float rs0 = 0.f, rs1 = 0.f;
#pragma unroll
        for (int nt = 0; nt < 8; nt++) {
            sacc[nt][0] = __expf(sacc[nt][0] - m0);
            sacc[nt][1] = __expf(sacc[nt][1] - m0);
            sacc[nt][2] = __expf(sacc[nt][2] - m1);
            sacc[nt][3] = __expf(sacc[nt][3] - m1);
            rs0 += sacc[nt][0] + sacc[nt][1];
            rs1 += sacc[nt][2] + sacc[nt][3];
        }
        rs0 += __shfl_xor_sync(0xffffffffu, rs0, 1);
        rs0 += __shfl_xor_sync(0xffffffffu, rs0, 2);
        rs1 += __shfl_xor_sync(0xffffffffu, rs1, 1);
        rs1 += __shfl_xor_sync(0xffffffffu, rs1, 2);
        l0 = l0 * cr0 + rs0;
        l1 = l1 * cr1 + rs1;

#pragma unroll
        for (int nt = 0; nt < 8; nt++) {
            oacc[nt][0] *= cr0; oacc[nt][1] *= cr0;
            oacc[nt][2] *= cr1; oacc[nt][3] *= cr1;
        }

        // ---- pack P fragments (C-frag layout == A-frag layout)
        uint32_t pa[4][4];
#pragma unroll
        for (int kt = 0; kt < 4; kt++) {
            pa[kt][0] = f2_to_h2(sacc[2 * kt][0], sacc[2 * kt][1]);
            pa[kt][1] = f2_to_h2(sacc[2 * kt][2], sacc[2 * kt][3]);
            pa[kt][2] = f2_to_h2(sacc[2 * kt + 1][0], sacc[2 * kt + 1][1]);
            pa[kt][3] = f2_to_h2(sacc[2 * kt + 1][2], sacc[2 * kt + 1][3]);
        }

        // ---- O += P @ V  (V^T fragments via ldmatrix.trans)
#pragma unroll
        for (int kt = 0; kt < 4; kt++) {
            uint32_t vf[8][2];
#pragma unroll
            for (int pr = 0; pr < 4; pr++)
                ldm_x4_t(vf[2 * pr][0], vf[2 * pr][1],
                         vf[2 * pr + 1][0], vf[2 * pr + 1][1],
                         sV + ((s * 64 + kt * 16 + a_row) * FA_PAD
                               + pr * 16 + a_ko) * 2);
#pragma unroll
            for (int nt = 0; nt < 8; nt++)
                mma_f16(oacc[nt][0], oacc[nt][1], oacc[nt][2], oacc[nt][3],
                        pa[kt][0], pa[kt][1], pa[kt][2], pa[kt][3],
                        vf[nt][0], vf[nt][1]);
        }

        __syncthreads();
        if (c + 2 < 16) load_kv(s, (c + 2) * 64);
    }

    // ---- epilogue: normalize and store
    const float li0 = 1.f / l0, li1 = 1.f / l1;
    const int row0 = b * LSEQ + i0 + w * 16 + g;
#pragma unroll
    for (int nt = 0; nt < 8; nt++) {
        const int col = h * 64 + nt * 8 + tig * 2;
        __half2 o0 = __floats2half2_rn(oacc[nt][0] * li0, oacc[nt][1] * li0);
        __half2 o1 = __floats2half2_rn(oacc[nt][2] * li1, oacc[nt][3] * li1);
        *(__half2*)(o_out + (size_t)row0 * DIM_ + col) = o0;
        *(__half2*)(o_out + (size_t)(row0 + 8) * DIM_ + col) = o1;
    }
}

// ---------------------------------------------------------------------------
// fp32 -> fp16 elementwise convert
// ---------------------------------------------------------------------------
__global__ __launch_bounds__(256)
void cvt_half(const float* __restrict__ in, half_t* __restrict__ out) {
    size_t i = ((size_t)blockIdx.x * 256 + threadIdx.x) * 4;
    float4 x = *(const float4*)(in + i);
    __half2 a, b;
    a.x = __float2half_rn(x.x); a.y = __float2half_rn(x.y);
    b.x = __float2half_rn(x.z); b.y = __float2half_rn(x.w);
    *(__half2*)(out + i) = a;
    *(__half2*)(out + i + 2) = b;
}

// ---------------------------------------------------------------------------
// Weight transpose+convert: fp32 [K,N] -> fp16 [N][K]
// ---------------------------------------------------------------------------
__global__ __launch_bounds__(256)
void wtrans_kernel(const float* __restrict__ w, half_t* __restrict__ o,
                   int K, int N) {
    __shared__ float t[32][33];
    int k0 = blockIdx.x * 32, n0 = blockIdx.y * 32;
    int tx = threadIdx.x & 31, ty = threadIdx.x >> 5;
    for (int i = ty; i < 32; i += 8)
        t[i][tx] = w[(size_t)(k0 + i) * N + n0 + tx];
    __syncthreads();
    for (int i = ty; i < 32; i += 8)
        o[(size_t)(n0 + i) * K + k0 + tx] = __float2half_rn(t[tx][i]);
}

// ---------------------------------------------------------------------------
// LayerNorm (+residual): out fp32 (optional) + fp16 copy (optional)
// ---------------------------------------------------------------------------
__global__ __launch_bounds__(256)
void ln_kernel(const float* __restrict__ in, const float* __restrict__ res,
               const float* __restrict__ g, const float* __restrict__ b,
               float* __restrict__ out_f, half_t* __restrict__ out_h) {
    const size_t row = blockIdx.x;
    const int t = threadIdx.x;
    float4 x = ((const float4*)(in + row * DIM_))[t];
    if (res) {
        float4 r = ((const float4*)(res + row * DIM_))[t];
        x.x += r.x; x.y += r.y; x.z += r.z; x.w += r.w;
    }
    float s = x.x + x.y + x.z + x.w;
    float ss = x.x*x.x + x.y*x.y + x.z*x.z + x.w*x.w;
#pragma unroll
    for (int o = 16; o > 0; o >>= 1) {
        s  += __shfl_down_sync(0xffffffffu, s, o);
        ss += __shfl_down_sync(0xffffffffu, ss, o);
    }
    __shared__ float shs[8], shss[8], shm, shr;
    int w = t >> 5, lane = t & 31;
    if (lane == 0) { shs[w] = s; shss[w] = ss; }
    __syncthreads();
    if (t == 0) {
        float S = 0, SS = 0;
#pragma unroll
        for (int i = 0; i < 8; i++) { S += shs[i]; SS += shss[i]; }
        float m = S * (1.f / DIM_);
        shm = m; shr = rsqrtf(SS * (1.f / DIM_) - m * m + EPS_);
    }
    __syncthreads();
    float m = shm, rs = shr;
    float4 gg = ((const float4*)g)[t], bb = ((const float4*)b)[t];
    float4 o4;
    o4.x = (x.x-m)*rs*gg.x + bb.x; o4.y = (x.y-m)*rs*gg.y + bb.y;
    o4.z = (x.z-m)*rs*gg.z + bb.z; o4.w = (x.w-m)*rs*gg.w + bb.w;
    if (out_f) ((float4*)(out_f + row * DIM_))[t] = o4;
    if (out_h) {
        __half2 a, bb2;
        a.x = __float2half_rn(o4.x); a.y = __float2half_rn(o4.y);
        bb2.x = __float2half_rn(o4.z); bb2.y = __float2half_rn(o4.w);
        size_t i = row * DIM_ + t * 4;
        *(__half2*)(out_h + i) = a;
        *(__half2*)(out_h + i + 2) = bb2;
    }
}

// ---------------------------------------------------------------------------
// Launch
// ---------------------------------------------------------------------------
#define GA(v, sym) cudaGetSymbolAddress((void**)&v, sym)

extern "C" void kernel_launch(void* const* d_in, const int* in_sizes, int n_in,
                              void* d_out, int out_size) {
    const float* x      = (const float*)d_in[0];
    const float* skip   = (const float*)d_in[1];
    const float* skip_w = (const float*)d_in[2];
    const float* skip_b = (const float*)d_in[3];
    const float* ln1_g  = (const float*)d_in[4];
    const float* ln1_b  = (const float*)d_in[5];
    const float* qkv_w  = (const float*)d_in[6];
    const float* proj_w = (const float*)d_in[7];
    const float* proj_b = (const float*)d_in[8];
    const float* ln2_g  = (const float*)d_in[9];
    const float* ln2_b  = (const float*)d_in[10];
    const float* fc1_w  = (const float*)d_in[11];
    const float* fc1_b  = (const float*)d_in[12];
    const float* fc2_w  = (const float*)d_in[13];
    const float* fc2_b  = (const float*)d_in[14];
    const float* ln3_g  = (const float*)d_in[15];
    const float* ln3_b  = (const float*)d_in[16];
    float* out = (float*)d_out;

    float *skipout, *xln1, *x2, *tmp;
    GA(skipout, g_skipout); GA(xln1, g_xln1); GA(x2, g_x2); GA(tmp, g_tmp);
    half_t *xh,*skh,*x1h,*qkvh,*obh,*x2h,*hh;
    GA(xh,g_xh); GA(skh,g_skh); GA(x1h,g_x1h); GA(qkvh,g_qkvh);
    GA(obh,g_obh); GA(x2h,g_x2h); GA(hh,g_hh);
    half_t *wsk,*wqkv,*wpr,*wf1,*wf2;
    GA(wsk,g_wsk); GA(wqkv,g_wqkv); GA(wpr,g_wpr); GA(wf1,g_wf1); GA(wf2,g_wf2);

    cudaFuncSetAttribute(fattn_kernel,
                         cudaFuncAttributeMaxDynamicSharedMemorySize, FA_SMEM);

    // ---- prep: transpose+convert weights, convert inputs
    wtrans_kernel<<<dim3(64,32), 256>>>(skip_w, wsk, 2*DIM_, DIM_);
    wtrans_kernel<<<dim3(32,96), 256>>>(qkv_w,  wqkv, DIM_, 3*DIM_);
    wtrans_kernel<<<dim3(32,32), 256>>>(proj_w, wpr,  DIM_, DIM_);
    wtrans_kernel<<<dim3(32,128),256>>>(fc1_w,  wf1,  DIM_, HID_);
    wtrans_kernel<<<dim3(128,32),256>>>(fc2_w,  wf2,  HID_, DIM_);
    cvt_half<<<NTOK*DIM_/1024, 256>>>(x,    xh);
    cvt_half<<<NTOK*DIM_/1024, 256>>>(skip, skh);

    GemmP p;

    // 1. skip-concat GEMM (K=2048, A switches x->skip at k=1024)
    memset(&p, 0, sizeof(p)); p.alpha = 1.f;
    p.a = xh; p.a2 = skh; p.b = wsk; p.bias = skip_b; p.out_f = skipout;
    p.K = 2048; p.lda = DIM_; p.ldb = 2048; p.ldc = DIM_; p.ksplit = 1024;
    gemm_fp16<128,true,true,false,true><<<dim3(8,32,1), 256>>>(p);
    // 2. LN1 -> xln1 f32 + x1h fp16
    ln_kernel<<<NTOK,256>>>(skipout, nullptr, ln1_g, ln1_b, xln1, x1h);
    // 3. QKV GEMM -> qkvh fp16
    memset(&p, 0, sizeof(p)); p.alpha = 1.f;
    p.a = x1h; p.b = wqkv; p.out_h = qkvh;
    p.K = DIM_; p.lda = DIM_; p.ldb = DIM_; p.ldc = 3*DIM_;
    gemm_fp16<128,false,false,false,false><<<dim3(24,32,1), 256>>>(p);
    // 4. fused flash attention -> obh fp16
    fattn_kernel<<<dim3(LSEQ/128, 64), 256, FA_SMEM>>>(qkvh, obh);
    // 5. proj -> tmp f32
    memset(&p, 0, sizeof(p)); p.alpha = 1.f;
    p.a = obh; p.b = wpr; p.bias = proj_b; p.out_f = tmp;
    p.K = DIM_; p.lda = DIM_; p.ldb = DIM_; p.ldc = DIM_;
    gemm_fp16<128,false,true,false,true><<<dim3(8,32,1), 256>>>(p);
    // 6. LN2 over (tmp + xln1) -> x2 f32 + x2h fp16
    ln_kernel<<<NTOK,256>>>(tmp, xln1, ln2_g, ln2_b, x2, x2h);
    // 7. fc1 + bias + GELU -> hh fp16
    memset(&p, 0, sizeof(p)); p.alpha = 1.f;
    p.a = x2h; p.b = wf1; p.bias = fc1_b; p.out_h = hh;
    p.K = DIM_; p.lda = DIM_; p.ldb = DIM_; p.ldc = HID_;
    gemm_fp16<128,false,true,true,false><<<dim3(32,32,1), 256>>>(p);
    // 8. fc2 -> tmp f32
    memset(&p, 0, sizeof(p)); p.alpha = 1.f;
    p.a = hh; p.b = wf2; p.bias = fc2_b; p.out_f = tmp;
    p.K = HID_; p.lda = HID_; p.ldb = HID_; p.ldc = DIM_;
    gemm_fp16<128,false,true,false,true><<<dim3(8,32,1), 256>>>(p);
    // 9. LN3 over (tmp + x2) -> out
    ln_kernel<<<NTOK,256>>>(tmp, x2, ln3_g, ln3_b, out, nullptr);
}